// round 2
// baseline (speedup 1.0000x reference)
#include <cuda_runtime.h>
#include <cstdint>

// Problem constants
#define B_     16
#define N_     256
#define DIM_   768
#define HEADS_ 12
#define DHEAD_ 64
#define BH_    (B_*HEADS_)      // 192
#define MAREA  2025
#define ROWS_  (B_*N_)          // 4096

// ---------------- scratch (static device globals; no allocations) ----------
__device__ float g_weff   [DIM_ * 3 * DIM_];           // [768][2304] composed weights
__device__ float g_biasqkv[3 * DIM_];                  // concat b_q|b_k|b_v
__device__ float g_qkvh   [(size_t)ROWS_ * 3 * DIM_];  // [4096][2304] qh|kh|vh
__device__ float g_karea  [(size_t)BH_ * MAREA * DHEAD_]; // [192][2025][64] means
__device__ float g_varea  [(size_t)BH_ * MAREA * DHEAD_]; // sums
__device__ float g_attn   [(size_t)ROWS_ * DIM_];      // [4096][768]

// ---------------- bias concat -------------------------------------------
__global__ void bias_concat_kernel(const float* __restrict__ bq,
                                   const float* __restrict__ bk,
                                   const float* __restrict__ bv) {
    int c = blockIdx.x * 768 + threadIdx.x;
    const float* src = (blockIdx.x == 0) ? bq : (blockIdx.x == 1) ? bk : bv;
    g_biasqkv[c] = src[threadIdx.x];
}

// ---------------- generic tiled SGEMM: C = A[MxK] @ B[KxN] (+bias) --------
// BM=BN=64, BK=16, 256 threads, 4x4 microtile. All dims divisible by 64/16.
__global__ __launch_bounds__(256)
void gemm64_kernel(const float* __restrict__ A, int lda,
                   const float* __restrict__ Bm, int ldb,
                   float* __restrict__ C, int ldc,
                   int K, const float* __restrict__ bias) {
    __shared__ float As[16][64];
    __shared__ float Bs[16][64];
    int t  = threadIdx.x;
    int tx = t & 15, ty = t >> 4;
    int n0 = blockIdx.x * 64;
    int m0 = blockIdx.y * 64;

    float acc[4][4];
#pragma unroll
    for (int i = 0; i < 4; ++i)
#pragma unroll
        for (int j = 0; j < 4; ++j) acc[i][j] = 0.f;

    int am  = t >> 2;          // 0..63  (A row within tile)
    int akq = (t & 3) * 4;     // k quad base
    int bk  = t >> 4;          // 0..15  (B k within tile)
    int bn  = (t & 15) * 4;    // n quad base

    const float* Ap = A  + (size_t)(m0 + am) * lda + akq;
    const float* Bp = Bm + (size_t)bk * ldb + n0 + bn;

    for (int k0 = 0; k0 < K; k0 += 16) {
        float4 av = *(const float4*)(Ap + k0);
        float4 bv = *(const float4*)(Bp + (size_t)k0 * ldb);
        __syncthreads();
        As[akq + 0][am] = av.x;
        As[akq + 1][am] = av.y;
        As[akq + 2][am] = av.z;
        As[akq + 3][am] = av.w;
        *(float4*)&Bs[bk][bn] = bv;
        __syncthreads();
#pragma unroll
        for (int k = 0; k < 16; ++k) {
            float4 a4 = *(const float4*)&As[k][ty * 4];
            float4 b4 = *(const float4*)&Bs[k][tx * 4];
            acc[0][0] += a4.x * b4.x; acc[0][1] += a4.x * b4.y;
            acc[0][2] += a4.x * b4.z; acc[0][3] += a4.x * b4.w;
            acc[1][0] += a4.y * b4.x; acc[1][1] += a4.y * b4.y;
            acc[1][2] += a4.y * b4.z; acc[1][3] += a4.y * b4.w;
            acc[2][0] += a4.z * b4.x; acc[2][1] += a4.z * b4.y;
            acc[2][2] += a4.z * b4.z; acc[2][3] += a4.z * b4.w;
            acc[3][0] += a4.w * b4.x; acc[3][1] += a4.w * b4.y;
            acc[3][2] += a4.w * b4.z; acc[3][3] += a4.w * b4.w;
        }
    }
#pragma unroll
    for (int i = 0; i < 4; ++i) {
        int row = m0 + ty * 4 + i;
#pragma unroll
        for (int j = 0; j < 4; ++j) {
            int col = n0 + tx * 4 + j;
            float v = acc[i][j];
            if (bias) v += bias[col];
            C[(size_t)row * ldc + col] = v;
        }
    }
}

// ---------------- area pooling via integral image ------------------------
// grid (192, 4): block = one bh, 16 channels. 256 threads.
__global__ __launch_bounds__(256)
void area_pool_kernel() {
    int bh = blockIdx.x;
    int cbase = blockIdx.y * 16;
    int b = bh / HEADS_, h = bh % HEADS_;
    __shared__ float sat[16][17][17];
    int t = threadIdx.x;

    const int cnts[9] = {256, 240, 224, 240, 225, 210, 224, 210, 196};

    for (int pass = 0; pass < 2; ++pass) {
        int off = (pass == 0) ? DIM_ : 2 * DIM_;   // kh at 768, vh at 1536
        const float* base = g_qkvh + (size_t)(b * N_) * (3 * DIM_) + off + h * DHEAD_ + cbase;

        // phase 1: row-wise prefix sums into sat[c][row+1][x+1]
        {
            int c = t & 15, row = t >> 4;
            if (row == 0)
                for (int x = 0; x < 17; ++x) sat[c][0][x] = 0.f;
            sat[c][row + 1][0] = 0.f;
            float acc = 0.f;
            for (int x = 0; x < 16; ++x) {
                acc += base[(size_t)(row * 16 + x) * (3 * DIM_) + c];
                sat[c][row + 1][x + 1] = acc;
            }
        }
        __syncthreads();
        // phase 2: column-wise prefix down rows
        {
            int c = t & 15, col = (t >> 4) + 1;    // cols 1..16
            float acc = 0.f;
            for (int y = 1; y <= 16; ++y) {
                acc += sat[c][y][col];
                sat[c][y][col] = acc;
            }
        }
        __syncthreads();
        // phase 3: area sums for all 2025 areas
        float* outbuf = (pass == 0) ? g_karea : g_varea;
        for (int m = t; m < MAREA; m += 256) {
            int rem = m, seg = 0;
            while (rem >= cnts[seg]) { rem -= cnts[seg]; ++seg; }
            int ah = seg / 3 + 1, aw = seg % 3 + 1;
            int w = 17 - aw;
            int y0 = rem / w, x0 = rem % w;
            float scale = (pass == 0) ? 1.f / (float)(ah * aw) : 1.f;
            size_t o = ((size_t)bh * MAREA + m) * DHEAD_ + cbase;
#pragma unroll
            for (int c = 0; c < 16; ++c) {
                float s = sat[c][y0 + ah][x0 + aw] - sat[c][y0][x0 + aw]
                        - sat[c][y0 + ah][x0]      + sat[c][y0][x0];
                outbuf[o + c] = s * scale;
            }
        }
        __syncthreads();
    }
}

// ---------------- fused flash-style area attention -----------------------
// grid (192, 2), 128 threads; one thread per query.
__global__ __launch_bounds__(128)
void attn_kernel() {
    int bh = blockIdx.x;
    int n  = blockIdx.y * 128 + threadIdx.x;
    int b = bh / HEADS_, h = bh % HEADS_;

    const float* qp = g_qkvh + (size_t)(b * N_ + n) * (3 * DIM_) + h * DHEAD_;
    float4 q[16];
#pragma unroll
    for (int i = 0; i < 16; ++i) q[i] = *(const float4*)(qp + i * 4);

    __shared__ float4 Ks[32][16];
    __shared__ float4 Vs[32][16];

    float4 o[16];
#pragma unroll
    for (int i = 0; i < 16; ++i) o[i] = make_float4(0.f, 0.f, 0.f, 0.f);
    float mrun = -1e30f, l = 0.f;

    const float* kb = g_karea + (size_t)bh * MAREA * DHEAD_;
    const float* vb = g_varea + (size_t)bh * MAREA * DHEAD_;

    for (int m0 = 0; m0 < MAREA; m0 += 32) {
        int cnt = min(32, MAREA - m0);
        __syncthreads();
        for (int e = threadIdx.x; e < cnt * 16; e += 128) {
            int r = e >> 4, c = e & 15;
            Ks[r][c] = *(const float4*)(kb + (size_t)(m0 + r) * DHEAD_ + c * 4);
            Vs[r][c] = *(const float4*)(vb + (size_t)(m0 + r) * DHEAD_ + c * 4);
        }
        __syncthreads();
        for (int mm = 0; mm < cnt; ++mm) {
            float s = 0.f;
#pragma unroll
            for (int i = 0; i < 16; ++i) {
                float4 kv = Ks[mm][i];
                s += q[i].x * kv.x + q[i].y * kv.y + q[i].z * kv.z + q[i].w * kv.w;
            }
            if (s > mrun) {             // rare: rescale history
                float sc = __expf(mrun - s);
                l *= sc;
#pragma unroll
                for (int i = 0; i < 16; ++i) {
                    o[i].x *= sc; o[i].y *= sc; o[i].z *= sc; o[i].w *= sc;
                }
                mrun = s;
            }
            float p = __expf(s - mrun);
            l += p;
#pragma unroll
            for (int i = 0; i < 16; ++i) {
                float4 vv = Vs[mm][i];
                o[i].x += p * vv.x; o[i].y += p * vv.y;
                o[i].z += p * vv.z; o[i].w += p * vv.w;
            }
        }
    }
    float invl = 1.f / l;
    float* op = g_attn + (size_t)(b * N_ + n) * DIM_ + h * DHEAD_;
#pragma unroll
    for (int i = 0; i < 16; ++i) {
        float4 v = o[i];
        v.x *= invl; v.y *= invl; v.z *= invl; v.w *= invl;
        *(float4*)(op + i * 4) = v;
    }
}

// ---------------- launch ---------------------------------------------------
extern "C" void kernel_launch(void* const* d_in, const int* in_sizes, int n_in,
                              void* d_out, int out_size) {
    const float* x     = (const float*)d_in[0];
    const float* w_qkv = (const float*)d_in[1];
    const float* w_q   = (const float*)d_in[2];
    const float* b_q   = (const float*)d_in[3];
    const float* w_k   = (const float*)d_in[4];
    const float* b_k   = (const float*)d_in[5];
    const float* w_v   = (const float*)d_in[6];
    const float* b_v   = (const float*)d_in[7];
    const float* w_o   = (const float*)d_in[8];
    const float* b_o   = (const float*)d_in[9];
    float* out = (float*)d_out;

    float* weff;   cudaGetSymbolAddress((void**)&weff,   g_weff);
    float* qkvh;   cudaGetSymbolAddress((void**)&qkvh,   g_qkvh);
    float* biasq;  cudaGetSymbolAddress((void**)&biasq,  g_biasqkv);
    float* attn;   cudaGetSymbolAddress((void**)&attn,   g_attn);

    // 1. concat qkv biases
    bias_concat_kernel<<<3, 768>>>(b_q, b_k, b_v);

    // 2. compose W_eff_{q,k,v} = w_qkv[:, seg] @ w_{q,k,v}   (768x768 each)
    {
        dim3 grid(768 / 64, 768 / 64);
        gemm64_kernel<<<grid, 256>>>(w_qkv +    0, 3 * DIM_, w_q, DIM_,
                                     weff +    0, 3 * DIM_, DIM_, nullptr);
        gemm64_kernel<<<grid, 256>>>(w_qkv +  768, 3 * DIM_, w_k, DIM_,
                                     weff +  768, 3 * DIM_, DIM_, nullptr);
        gemm64_kernel<<<grid, 256>>>(w_qkv + 1536, 3 * DIM_, w_v, DIM_,
                                     weff + 1536, 3 * DIM_, DIM_, nullptr);
    }

    // 3. qh|kh|vh = x @ W_eff + bias   ([4096,768] @ [768,2304])
    {
        dim3 grid((3 * DIM_) / 64, ROWS_ / 64);
        gemm64_kernel<<<grid, 256>>>(x, DIM_, weff, 3 * DIM_,
                                     qkvh, 3 * DIM_, DIM_, biasq);
    }

    // 4. area pooling (integral image): k means + v sums
    {
        dim3 grid(BH_, DHEAD_ / 16);
        area_pool_kernel<<<grid, 256>>>();
    }

    // 5. fused attention with online softmax
    {
        dim3 grid(BH_, N_ / 128);
        attn_kernel<<<grid, 128>>>();
    }

    // 6. output projection: out = attn @ w_o + b_o
    {
        dim3 grid(DIM_ / 64, ROWS_ / 64);
        gemm64_kernel<<<grid, 256>>>(attn, DIM_, w_o, DIM_,
                                     out, DIM_, DIM_, b_o);
    }
}

// round 4
// speedup vs baseline: 1.4661x; 1.4661x over previous
#include <cuda_runtime.h>
#include <cuda_bf16.h>
#include <cstdint>

#define B_     16
#define N_     256
#define DIM_   768
#define HEADS_ 12
#define DHEAD_ 64
#define BH_    192
#define MAREA  2025
#define MPAD   2048
#define ROWS_  4096
#define K3     2304

typedef __nv_bfloat16 bf16;

// ---------------- device global scratch ----------------
__device__ float g_biasqkv[K3];
__device__ bf16  g_x_hi[ROWS_*DIM_],   g_x_lo[ROWS_*DIM_];
__device__ bf16  g_wqkv_hi[DIM_*K3],   g_wqkv_lo[DIM_*K3];
__device__ bf16  g_wT_hi[3*DIM_*DIM_], g_wT_lo[3*DIM_*DIM_];
__device__ bf16  g_woT_hi[DIM_*DIM_],  g_woT_lo[DIM_*DIM_];
__device__ bf16  g_weffT_hi[K3*DIM_],  g_weffT_lo[K3*DIM_];
__device__ float g_qkvh_f[(size_t)ROWS_*K3];
__device__ bf16  g_qkvh_hi[(size_t)ROWS_*K3], g_qkvh_lo[(size_t)ROWS_*K3];
__device__ bf16  g_ka_hi[(size_t)BH_*MPAD*DHEAD_], g_ka_lo[(size_t)BH_*MPAD*DHEAD_];
__device__ bf16  g_vt_hi[(size_t)BH_*DHEAD_*MPAD], g_vt_lo[(size_t)BH_*DHEAD_*MPAD];
__device__ bf16  g_attn_hi[(size_t)ROWS_*DIM_],    g_attn_lo[(size_t)ROWS_*DIM_];

// ---------------- helpers ----------------
__device__ __forceinline__ uint32_t packhi2(float x, float y) {
    __nv_bfloat162 t = __floats2bfloat162_rn(x, y);
    return *(uint32_t*)&t;
}
__device__ __forceinline__ uint32_t packlo2(float x, float y, uint32_t hp) {
    __nv_bfloat162 h = *(__nv_bfloat162*)&hp;
    __nv_bfloat162 t = __floats2bfloat162_rn(x - __bfloat162float(h.x),
                                             y - __bfloat162float(h.y));
    return *(uint32_t*)&t;
}

// d[4] += A(m16k16 bf16, regs a[4]) * B(k16n8 bf16, regs b0,b1)
#define MMA16(d, a, b0, b1) \
    asm volatile("mma.sync.aligned.m16n8k16.row.col.f32.bf16.bf16.f32 " \
        "{%0,%1,%2,%3}, {%4,%5,%6,%7}, {%8,%9}, {%0,%1,%2,%3};" \
        : "+f"((d)[0]), "+f"((d)[1]), "+f"((d)[2]), "+f"((d)[3]) \
        : "r"((a)[0]), "r"((a)[1]), "r"((a)[2]), "r"((a)[3]), "r"(b0), "r"(b1))

// ---------------- small elementwise kernels ----------------
__global__ void bias_concat_kernel(const float* bq, const float* bk, const float* bv) {
    int c = blockIdx.x * 768 + threadIdx.x;
    const float* s = (blockIdx.x == 0) ? bq : (blockIdx.x == 1) ? bk : bv;
    g_biasqkv[c] = s[threadIdx.x];
}

__global__ void conv_kernel(const float* __restrict__ src, bf16* __restrict__ hi,
                            bf16* __restrict__ lo, int n) {
    int i = blockIdx.x * 256 + threadIdx.x;
    if (i < n) {
        float v = src[i];
        bf16 h = __float2bfloat16(v);
        hi[i] = h;
        lo[i] = __float2bfloat16(v - __bfloat162float(h));
    }
}

__global__ void convT_kernel(const float* __restrict__ src, bf16* __restrict__ hi,
                             bf16* __restrict__ lo) {
    __shared__ float tile[32][33];
    int c0 = blockIdx.x * 32, r0 = blockIdx.y * 32;
    int tx = threadIdx.x, ty = threadIdx.y;
#pragma unroll
    for (int i = 0; i < 4; ++i)
        tile[ty + i * 8][tx] = src[(size_t)(r0 + ty + i * 8) * DIM_ + c0 + tx];
    __syncthreads();
#pragma unroll
    for (int i = 0; i < 4; ++i) {
        float v = tile[tx][ty + i * 8];
        size_t o = (size_t)(c0 + ty + i * 8) * DIM_ + r0 + tx;
        bf16 h = __float2bfloat16(v);
        hi[o] = h;
        lo[o] = __float2bfloat16(v - __bfloat162float(h));
    }
}

// ---------------- generic 128x128 warp-MMA GEMM, 3-term hi/lo split -------
// C[M][N] = A[M][K] @ B[N][K]^T ; both operands K-major, K % 64 == 0.
// 256 threads = 8 warps in 4(m) x 2(n); warp tile 32x64.
__global__ __launch_bounds__(256)
void gemm128_kernel(const bf16* __restrict__ Ah, const bf16* __restrict__ Al, int lda,
                    const bf16* __restrict__ Bh, const bf16* __restrict__ Bl, int ldb,
                    float* __restrict__ Cf, bf16* __restrict__ Chi, bf16* __restrict__ Clo,
                    int ldc, int K, const float* __restrict__ bias) {
    extern __shared__ bf16 sm[];
    bf16* AsH = sm;              // 128 x 72
    bf16* AsL = sm + 9216;
    bf16* BsH = sm + 18432;
    bf16* BsL = sm + 27648;
    int tid = threadIdx.x, lane = tid & 31, wid = tid >> 5;
    int g = lane >> 2, tig = lane & 3;
    int wm = (wid >> 1) * 32, wn = (wid & 1) * 64;
    int m0 = blockIdx.y * 128, n0 = blockIdx.x * 128;

    float acc[2][8][4];
#pragma unroll
    for (int mt = 0; mt < 2; ++mt)
#pragma unroll
        for (int nt = 0; nt < 8; ++nt)
#pragma unroll
            for (int i = 0; i < 4; ++i) acc[mt][nt][i] = 0.f;

    for (int c = 0; c < K; c += 64) {
        __syncthreads();
#pragma unroll
        for (int it = 0; it < 4; ++it) {
            int idx = tid + it * 256;
            int row = idx >> 3, seg = (idx & 7) * 8;
            size_t ga = (size_t)(m0 + row) * lda + c + seg;
            size_t gb = (size_t)(n0 + row) * ldb + c + seg;
            int so = row * 72 + seg;
            *(uint4*)(AsH + so) = *(const uint4*)(Ah + ga);
            *(uint4*)(AsL + so) = *(const uint4*)(Al + ga);
            *(uint4*)(BsH + so) = *(const uint4*)(Bh + gb);
            *(uint4*)(BsL + so) = *(const uint4*)(Bl + gb);
        }
        __syncthreads();
#pragma unroll
        for (int ks = 0; ks < 4; ++ks) {
            uint32_t ah[2][4], al[2][4];
#pragma unroll
            for (int mt = 0; mt < 2; ++mt) {
                int base = (wm + mt * 16 + g) * 72 + ks * 16 + 2 * tig;
                ah[mt][0] = *(uint32_t*)(AsH + base);
                ah[mt][1] = *(uint32_t*)(AsH + base + 8 * 72);
                ah[mt][2] = *(uint32_t*)(AsH + base + 8);
                ah[mt][3] = *(uint32_t*)(AsH + base + 8 * 72 + 8);
                al[mt][0] = *(uint32_t*)(AsL + base);
                al[mt][1] = *(uint32_t*)(AsL + base + 8 * 72);
                al[mt][2] = *(uint32_t*)(AsL + base + 8);
                al[mt][3] = *(uint32_t*)(AsL + base + 8 * 72 + 8);
            }
#pragma unroll
            for (int nt = 0; nt < 8; ++nt) {
                int bb = (wn + nt * 8 + g) * 72 + ks * 16 + 2 * tig;
                uint32_t bh0 = *(uint32_t*)(BsH + bb), bh1 = *(uint32_t*)(BsH + bb + 8);
                uint32_t bl0 = *(uint32_t*)(BsL + bb), bl1 = *(uint32_t*)(BsL + bb + 8);
#pragma unroll
                for (int mt = 0; mt < 2; ++mt) {
                    MMA16(acc[mt][nt], ah[mt], bh0, bh1);
                    MMA16(acc[mt][nt], ah[mt], bl0, bl1);
                    MMA16(acc[mt][nt], al[mt], bh0, bh1);
                }
            }
        }
    }
    // epilogue
#pragma unroll
    for (int mt = 0; mt < 2; ++mt)
#pragma unroll
        for (int nt = 0; nt < 8; ++nt) {
            int row = m0 + wm + mt * 16 + g;
            int col = n0 + wn + nt * 8 + 2 * tig;
            float v0 = acc[mt][nt][0], v1 = acc[mt][nt][1];
            float v2 = acc[mt][nt][2], v3 = acc[mt][nt][3];
            if (bias) {
                float b0v = bias[col], b1v = bias[col + 1];
                v0 += b0v; v1 += b1v; v2 += b0v; v3 += b1v;
            }
            if (Cf) {
                *(float2*)(Cf + (size_t)row * ldc + col)       = make_float2(v0, v1);
                *(float2*)(Cf + (size_t)(row + 8) * ldc + col) = make_float2(v2, v3);
            }
            if (Chi) {
                uint32_t h01 = packhi2(v0, v1), h23 = packhi2(v2, v3);
                *(uint32_t*)(Chi + (size_t)row * ldc + col)       = h01;
                *(uint32_t*)(Chi + (size_t)(row + 8) * ldc + col) = h23;
                *(uint32_t*)(Clo + (size_t)row * ldc + col)       = packlo2(v0, v1, h01);
                *(uint32_t*)(Clo + (size_t)(row + 8) * ldc + col) = packlo2(v2, v3, h23);
            }
        }
}

// ---------------- area pooling (integral image) -> bf16 hi/lo ------------
__global__ __launch_bounds__(256)
void pool_kernel() {
    int bh = blockIdx.x;
    int b = bh / HEADS_, h = bh % HEADS_;
    extern __shared__ float sat[];  // [64][17*17]
    int t = threadIdx.x;
    const int cnts[9] = {256, 240, 224, 240, 225, 210, 224, 210, 196};

    for (int pass = 0; pass < 2; ++pass) {
        const float* base = g_qkvh_f + (size_t)(b * N_) * K3 + (pass ? 2 * DIM_ : DIM_) + h * DHEAD_;
        for (int it = 0; it < 4; ++it) {
            int task = t + it * 256;
            int ch = task & 63, row = task >> 6;
            if (row == 0)
                for (int x = 0; x < 17; ++x) sat[ch * 289 + x] = 0.f;
            float acc = 0.f;
            sat[ch * 289 + (row + 1) * 17] = 0.f;
            for (int x = 0; x < 16; ++x) {
                acc += base[(size_t)(row * 16 + x) * K3 + ch];
                sat[ch * 289 + (row + 1) * 17 + x + 1] = acc;
            }
        }
        __syncthreads();
        for (int it = 0; it < 4; ++it) {
            int task = t + it * 256;
            int ch = task >> 4, col = (task & 15) + 1;
            float acc = 0.f;
            for (int y = 1; y <= 16; ++y) {
                acc += sat[ch * 289 + y * 17 + col];
                sat[ch * 289 + y * 17 + col] = acc;
            }
        }
        __syncthreads();
        for (int m = t; m < MPAD; m += 256) {
            float scale = 0.f;
            int y0 = 0, x0 = 0, ah = 1, aw = 1;
            bool valid = (m < MAREA);
            if (valid) {
                int rem = m, seg = 0;
                while (rem >= cnts[seg]) { rem -= cnts[seg]; ++seg; }
                ah = seg / 3 + 1; aw = seg % 3 + 1;
                int w = 17 - aw;
                y0 = rem / w; x0 = rem % w;
                scale = (pass == 0) ? 1.f / (float)(ah * aw) : 1.f;
            }
            for (int c = 0; c < 64; ++c) {
                float s = 0.f;
                if (valid) {
                    s = sat[c * 289 + (y0 + ah) * 17 + x0 + aw] - sat[c * 289 + y0 * 17 + x0 + aw]
                      - sat[c * 289 + (y0 + ah) * 17 + x0]      + sat[c * 289 + y0 * 17 + x0];
                    s *= scale;
                }
                bf16 hi = __float2bfloat16(s);
                bf16 lo = __float2bfloat16(s - __bfloat162float(hi));
                if (pass == 0) {
                    size_t o = ((size_t)bh * MPAD + m) * DHEAD_ + c;
                    g_ka_hi[o] = hi; g_ka_lo[o] = lo;
                } else {
                    size_t o = ((size_t)bh * DHEAD_ + c) * MPAD + m;
                    g_vt_hi[o] = hi; g_vt_lo[o] = lo;
                }
            }
        }
        __syncthreads();
    }
}

// ---------------- fused warp-MMA attention --------------------------------
// grid (BH_, 2): CTA = (bh, 128 queries). 8 warps: 4(m: 32q) x 2(n: 64 areas).
__global__ __launch_bounds__(256)
void attn_kernel() {
    extern __shared__ bf16 sm[];
    bf16* Qh = sm;             // 128 x 72
    bf16* Ql = sm + 9216;
    bf16* Kh = sm + 18432;     // 128 x 72 (areas x d)
    bf16* Kl = sm + 27648;
    bf16* Vh = sm + 36864;     // 64 x 136 (d x areas)
    bf16* Vl = sm + 45568;
    int tid = threadIdx.x, lane = tid & 31, wid = tid >> 5;
    int g = lane >> 2, tig = lane & 3;
    int wm = (wid >> 1) * 32, wn = wid & 1;
    int bh = blockIdx.x, q0 = blockIdx.y * 128;
    int b = bh / HEADS_, h = bh % HEADS_;

    // load Q tile (persists)
#pragma unroll
    for (int it = 0; it < 4; ++it) {
        int idx = tid + it * 256;
        int row = idx >> 3, seg = (idx & 7) * 8;
        size_t src = (size_t)(b * N_ + q0 + row) * K3 + h * 64 + seg;
        *(uint4*)(Qh + row * 72 + seg) = *(const uint4*)(g_qkvh_hi + src);
        *(uint4*)(Ql + row * 72 + seg) = *(const uint4*)(g_qkvh_lo + src);
    }

    const bf16* kaH = g_ka_hi + (size_t)bh * MPAD * 64;
    const bf16* kaL = g_ka_lo + (size_t)bh * MPAD * 64;
    const bf16* vtH = g_vt_hi + (size_t)bh * 64 * MPAD;
    const bf16* vtL = g_vt_lo + (size_t)bh * 64 * MPAD;

    float accO[2][8][4];
#pragma unroll
    for (int mt = 0; mt < 2; ++mt)
#pragma unroll
        for (int nt = 0; nt < 8; ++nt)
#pragma unroll
            for (int i = 0; i < 4; ++i) accO[mt][nt][i] = 0.f;
    float lsum[2][2] = {{0.f, 0.f}, {0.f, 0.f}};

    for (int t = 0; t < MPAD / 128; ++t) {
        __syncthreads();
#pragma unroll
        for (int it = 0; it < 4; ++it) {
            int idx = tid + it * 256;
            int row = idx >> 3, seg = (idx & 7) * 8;
            size_t src = (size_t)(t * 128 + row) * 64 + seg;
            *(uint4*)(Kh + row * 72 + seg) = *(const uint4*)(kaH + src);
            *(uint4*)(Kl + row * 72 + seg) = *(const uint4*)(kaL + src);
            int vrow = idx >> 4, vseg = (idx & 15) * 8;
            size_t vsrc = (size_t)vrow * MPAD + t * 128 + vseg;
            *(uint4*)(Vh + vrow * 136 + vseg) = *(const uint4*)(vtH + vsrc);
            *(uint4*)(Vl + vrow * 136 + vseg) = *(const uint4*)(vtL + vsrc);
        }
        __syncthreads();

        // ---- QK ----
        float s[2][8][4];
#pragma unroll
        for (int mt = 0; mt < 2; ++mt)
#pragma unroll
            for (int nt = 0; nt < 8; ++nt)
#pragma unroll
                for (int i = 0; i < 4; ++i) s[mt][nt][i] = 0.f;
#pragma unroll
        for (int ks = 0; ks < 4; ++ks) {
            uint32_t qh[2][4], ql[2][4];
#pragma unroll
            for (int mt = 0; mt < 2; ++mt) {
                int base = (wm + mt * 16 + g) * 72 + ks * 16 + 2 * tig;
                qh[mt][0] = *(uint32_t*)(Qh + base);
                qh[mt][1] = *(uint32_t*)(Qh + base + 8 * 72);
                qh[mt][2] = *(uint32_t*)(Qh + base + 8);
                qh[mt][3] = *(uint32_t*)(Qh + base + 8 * 72 + 8);
                ql[mt][0] = *(uint32_t*)(Ql + base);
                ql[mt][1] = *(uint32_t*)(Ql + base + 8 * 72);
                ql[mt][2] = *(uint32_t*)(Ql + base + 8);
                ql[mt][3] = *(uint32_t*)(Ql + base + 8 * 72 + 8);
            }
#pragma unroll
            for (int nt = 0; nt < 8; ++nt) {
                int bb = (wn * 64 + nt * 8 + g) * 72 + ks * 16 + 2 * tig;
                uint32_t bh0 = *(uint32_t*)(Kh + bb), bh1 = *(uint32_t*)(Kh + bb + 8);
                uint32_t bl0 = *(uint32_t*)(Kl + bb), bl1 = *(uint32_t*)(Kl + bb + 8);
#pragma unroll
                for (int mt = 0; mt < 2; ++mt) {
                    MMA16(s[mt][nt], qh[mt], bh0, bh1);
                    MMA16(s[mt][nt], qh[mt], bl0, bl1);
                    MMA16(s[mt][nt], ql[mt], bh0, bh1);
                }
            }
        }

        // ---- softmax (no max subtraction; logits are small) ----
#pragma unroll
        for (int mt = 0; mt < 2; ++mt)
#pragma unroll
            for (int nt = 0; nt < 8; ++nt) {
                int cb = t * 128 + wn * 64 + nt * 8 + 2 * tig;
                float p0 = (cb     < MAREA) ? __expf(s[mt][nt][0]) : 0.f;
                float p1 = (cb + 1 < MAREA) ? __expf(s[mt][nt][1]) : 0.f;
                float p2 = (cb     < MAREA) ? __expf(s[mt][nt][2]) : 0.f;
                float p3 = (cb + 1 < MAREA) ? __expf(s[mt][nt][3]) : 0.f;
                s[mt][nt][0] = p0; s[mt][nt][1] = p1;
                s[mt][nt][2] = p2; s[mt][nt][3] = p3;
                lsum[mt][0] += p0 + p1;
                lsum[mt][1] += p2 + p3;
            }

        // ---- PV: accO += P @ V^T (P fragments built in-register) ----
#pragma unroll
        for (int kk = 0; kk < 4; ++kk) {
            uint32_t pah[2][4], pal[2][4];
#pragma unroll
            for (int mt = 0; mt < 2; ++mt) {
                pah[mt][0] = packhi2(s[mt][2 * kk][0],     s[mt][2 * kk][1]);
                pah[mt][1] = packhi2(s[mt][2 * kk][2],     s[mt][2 * kk][3]);
                pah[mt][2] = packhi2(s[mt][2 * kk + 1][0], s[mt][2 * kk + 1][1]);
                pah[mt][3] = packhi2(s[mt][2 * kk + 1][2], s[mt][2 * kk + 1][3]);
                pal[mt][0] = packlo2(s[mt][2 * kk][0],     s[mt][2 * kk][1],     pah[mt][0]);
                pal[mt][1] = packlo2(s[mt][2 * kk][2],     s[mt][2 * kk][3],     pah[mt][1]);
                pal[mt][2] = packlo2(s[mt][2 * kk + 1][0], s[mt][2 * kk + 1][1], pah[mt][2]);
                pal[mt][3] = packlo2(s[mt][2 * kk + 1][2], s[mt][2 * kk + 1][3], pah[mt][3]);
            }
#pragma unroll
            for (int nt = 0; nt < 8; ++nt) {
                int vb = (nt * 8 + g) * 136 + wn * 64 + kk * 16 + 2 * tig;
                uint32_t bh0 = *(uint32_t*)(Vh + vb), bh1 = *(uint32_t*)(Vh + vb + 8);
                uint32_t bl0 = *(uint32_t*)(Vl + vb), bl1 = *(uint32_t*)(Vl + vb + 8);
#pragma unroll
                for (int mt = 0; mt < 2; ++mt) {
                    MMA16(accO[mt][nt], pah[mt], bh0, bh1);
                    MMA16(accO[mt][nt], pah[mt], bl0, bl1);
                    MMA16(accO[mt][nt], pal[mt], bh0, bh1);
                }
            }
        }
    }

    // ---- reduce l over tig ----
#pragma unroll
    for (int mt = 0; mt < 2; ++mt)
#pragma unroll
        for (int r = 0; r < 2; ++r) {
            lsum[mt][r] += __shfl_xor_sync(0xFFFFFFFF, lsum[mt][r], 1);
            lsum[mt][r] += __shfl_xor_sync(0xFFFFFFFF, lsum[mt][r], 2);
        }

    __syncthreads();
    float* Ored = (float*)Kh;   // 32 KB, overlays K region
    float* lred = (float*)Vh;   // overlays V region
    if (wn == 1) {
#pragma unroll
        for (int mt = 0; mt < 2; ++mt) {
            int r0 = wm + mt * 16 + g;
#pragma unroll
            for (int nt = 0; nt < 8; ++nt) {
                int cc = nt * 8 + 2 * tig;
                Ored[r0 * 64 + cc]           = accO[mt][nt][0];
                Ored[r0 * 64 + cc + 1]       = accO[mt][nt][1];
                Ored[(r0 + 8) * 64 + cc]     = accO[mt][nt][2];
                Ored[(r0 + 8) * 64 + cc + 1] = accO[mt][nt][3];
            }
            if (tig == 0) {
                lred[r0]     = lsum[mt][0];
                lred[r0 + 8] = lsum[mt][1];
            }
        }
    }
    __syncthreads();
    if (wn == 0) {
#pragma unroll
        for (int mt = 0; mt < 2; ++mt) {
            int r0 = wm + mt * 16 + g;
            float inv0 = 1.f / (lsum[mt][0] + lred[r0]);
            float inv1 = 1.f / (lsum[mt][1] + lred[r0 + 8]);
            size_t orow0 = (size_t)(b * N_ + q0 + r0) * DIM_ + h * 64;
            size_t orow1 = (size_t)(b * N_ + q0 + r0 + 8) * DIM_ + h * 64;
#pragma unroll
            for (int nt = 0; nt < 8; ++nt) {
                int cc = nt * 8 + 2 * tig;
                float o0 = (accO[mt][nt][0] + Ored[r0 * 64 + cc])           * inv0;
                float o1 = (accO[mt][nt][1] + Ored[r0 * 64 + cc + 1])       * inv0;
                float o2 = (accO[mt][nt][2] + Ored[(r0 + 8) * 64 + cc])     * inv1;
                float o3 = (accO[mt][nt][3] + Ored[(r0 + 8) * 64 + cc + 1]) * inv1;
                uint32_t h01 = packhi2(o0, o1), h23 = packhi2(o2, o3);
                *(uint32_t*)(g_attn_hi + orow0 + cc) = h01;
                *(uint32_t*)(g_attn_hi + orow1 + cc) = h23;
                *(uint32_t*)(g_attn_lo + orow0 + cc) = packlo2(o0, o1, h01);
                *(uint32_t*)(g_attn_lo + orow1 + cc) = packlo2(o2, o3, h23);
            }
        }
    }
}

// ---------------- launch ---------------------------------------------------
extern "C" void kernel_launch(void* const* d_in, const int* in_sizes, int n_in,
                              void* d_out, int out_size) {
    const float* x     = (const float*)d_in[0];
    const float* w_qkv = (const float*)d_in[1];
    const float* w_q   = (const float*)d_in[2];
    const float* b_q   = (const float*)d_in[3];
    const float* w_k   = (const float*)d_in[4];
    const float* b_k   = (const float*)d_in[5];
    const float* w_v   = (const float*)d_in[6];
    const float* b_v   = (const float*)d_in[7];
    const float* w_o   = (const float*)d_in[8];
    const float* b_o   = (const float*)d_in[9];
    float* out = (float*)d_out;

    cudaFuncSetAttribute(gemm128_kernel, cudaFuncAttributeMaxDynamicSharedMemorySize, 73728);
    cudaFuncSetAttribute(attn_kernel,    cudaFuncAttributeMaxDynamicSharedMemorySize, 108544);
    cudaFuncSetAttribute(pool_kernel,    cudaFuncAttributeMaxDynamicSharedMemorySize, 73984);

    bf16 *x_hi, *x_lo, *wqkv_hi, *wqkv_lo, *wT_hi, *wT_lo, *woT_hi, *woT_lo;
    bf16 *weffT_hi, *weffT_lo, *qkvh_hi, *qkvh_lo, *attn_hi, *attn_lo;
    float *qkvh_f, *biasqkv;
    cudaGetSymbolAddress((void**)&x_hi, g_x_hi);       cudaGetSymbolAddress((void**)&x_lo, g_x_lo);
    cudaGetSymbolAddress((void**)&wqkv_hi, g_wqkv_hi); cudaGetSymbolAddress((void**)&wqkv_lo, g_wqkv_lo);
    cudaGetSymbolAddress((void**)&wT_hi, g_wT_hi);     cudaGetSymbolAddress((void**)&wT_lo, g_wT_lo);
    cudaGetSymbolAddress((void**)&woT_hi, g_woT_hi);   cudaGetSymbolAddress((void**)&woT_lo, g_woT_lo);
    cudaGetSymbolAddress((void**)&weffT_hi, g_weffT_hi); cudaGetSymbolAddress((void**)&weffT_lo, g_weffT_lo);
    cudaGetSymbolAddress((void**)&qkvh_f, g_qkvh_f);
    cudaGetSymbolAddress((void**)&qkvh_hi, g_qkvh_hi); cudaGetSymbolAddress((void**)&qkvh_lo, g_qkvh_lo);
    cudaGetSymbolAddress((void**)&attn_hi, g_attn_hi); cudaGetSymbolAddress((void**)&attn_lo, g_attn_lo);
    cudaGetSymbolAddress((void**)&biasqkv, g_biasqkv);

    // 1. bias concat + conversions
    bias_concat_kernel<<<3, 768>>>(b_q, b_k, b_v);
    conv_kernel<<<(ROWS_ * DIM_ + 255) / 256, 256>>>(x, x_hi, x_lo, ROWS_ * DIM_);
    conv_kernel<<<(DIM_ * K3 + 255) / 256, 256>>>(w_qkv, wqkv_hi, wqkv_lo, DIM_ * K3);
    {
        dim3 g(24, 24), blk(32, 8);
        convT_kernel<<<g, blk>>>(w_q, wT_hi,                   wT_lo);
        convT_kernel<<<g, blk>>>(w_k, wT_hi + DIM_ * DIM_,     wT_lo + DIM_ * DIM_);
        convT_kernel<<<g, blk>>>(w_v, wT_hi + 2 * DIM_ * DIM_, wT_lo + 2 * DIM_ * DIM_);
        convT_kernel<<<g, blk>>>(w_o, woT_hi, woT_lo);
    }

    // 2. compose W_eff^T[seg] = w_seg^T @ w_qkv_seg^T  (768x768, K=768)
    for (int seg = 0; seg < 3; ++seg) {
        dim3 g(6, 6);
        gemm128_kernel<<<g, 256, 73728>>>(
            wT_hi + (size_t)seg * DIM_ * DIM_, wT_lo + (size_t)seg * DIM_ * DIM_, DIM_,
            wqkv_hi + seg * DIM_, wqkv_lo + seg * DIM_, K3,
            nullptr,
            weffT_hi + (size_t)seg * DIM_ * DIM_, weffT_lo + (size_t)seg * DIM_ * DIM_,
            DIM_, DIM_, nullptr);
    }

    // 3. qh|kh|vh = x @ W_eff + bias  ([4096,768] @ [768,2304])
    {
        dim3 g(K3 / 128, ROWS_ / 128);
        gemm128_kernel<<<g, 256, 73728>>>(x_hi, x_lo, DIM_, weffT_hi, weffT_lo, DIM_,
                                          qkvh_f, qkvh_hi, qkvh_lo, K3, DIM_, biasqkv);
    }

    // 4. area pooling -> K means + V^T sums (bf16 hi/lo)
    pool_kernel<<<BH_, 256, 73984>>>();

    // 5. fused warp-MMA attention
    {
        dim3 g(BH_, 2);
        attn_kernel<<<g, 256, 108544>>>();
    }

    // 6. out = attn @ w_o + b_o
    {
        dim3 g(DIM_ / 128, ROWS_ / 128);
        gemm128_kernel<<<g, 256, 73728>>>(attn_hi, attn_lo, DIM_, woT_hi, woT_lo, DIM_,
                                          out, nullptr, nullptr, DIM_, DIM_, b_o);
    }
}

// round 5
// speedup vs baseline: 1.5392x; 1.0499x over previous
#include <cuda_runtime.h>
#include <cuda_bf16.h>
#include <cstdint>

#define B_     16
#define N_     256
#define DIM_   768
#define HEADS_ 12
#define DHEAD_ 64
#define BH_    192
#define MAREA  2025
#define MPAD   2048
#define ROWS_  4096
#define K3     2304

typedef __nv_bfloat16 bf16;

// ---------------- device global scratch ----------------
__device__ float g_biasqkv[K3];
__device__ bf16  g_x_hi[ROWS_*DIM_],   g_x_lo[ROWS_*DIM_];
__device__ bf16  g_wqkv_hi[DIM_*K3],   g_wqkv_lo[DIM_*K3];
__device__ bf16  g_wT_hi[3*DIM_*DIM_], g_wT_lo[3*DIM_*DIM_];
__device__ bf16  g_woT_hi[DIM_*DIM_],  g_woT_lo[DIM_*DIM_];
__device__ bf16  g_weffT_hi[K3*DIM_],  g_weffT_lo[K3*DIM_];
__device__ float g_qkvh_f[(size_t)ROWS_*K3];
__device__ bf16  g_qkvh_hi[(size_t)ROWS_*K3], g_qkvh_lo[(size_t)ROWS_*K3];
__device__ bf16  g_ka_hi[(size_t)BH_*MPAD*DHEAD_], g_ka_lo[(size_t)BH_*MPAD*DHEAD_];
__device__ bf16  g_vt_hi[(size_t)BH_*DHEAD_*MPAD], g_vt_lo[(size_t)BH_*DHEAD_*MPAD];
__device__ bf16  g_attn_hi[(size_t)ROWS_*DIM_],    g_attn_lo[(size_t)ROWS_*DIM_];

// ---------------- helpers ----------------
__device__ __forceinline__ uint32_t smem_u32(const void* p) {
    uint32_t a;
    asm("{ .reg .u64 t; cvta.to.shared.u64 t, %1; cvt.u32.u64 %0, t; }" : "=r"(a) : "l"(p));
    return a;
}
__device__ __forceinline__ uint32_t packhi2(float x, float y) {
    __nv_bfloat162 t = __floats2bfloat162_rn(x, y);
    return *(uint32_t*)&t;
}
__device__ __forceinline__ uint32_t packlo2(float x, float y, uint32_t hp) {
    __nv_bfloat162 h = *(__nv_bfloat162*)&hp;
    __nv_bfloat162 t = __floats2bfloat162_rn(x - __bfloat162float(h.x),
                                             y - __bfloat162float(h.y));
    return *(uint32_t*)&t;
}

#define MMA16(d, a, b0, b1) \
    asm volatile("mma.sync.aligned.m16n8k16.row.col.f32.bf16.bf16.f32 " \
        "{%0,%1,%2,%3}, {%4,%5,%6,%7}, {%8,%9}, {%0,%1,%2,%3};" \
        : "+f"((d)[0]), "+f"((d)[1]), "+f"((d)[2]), "+f"((d)[3]) \
        : "r"((a)[0]), "r"((a)[1]), "r"((a)[2]), "r"((a)[3]), "r"(b0), "r"(b1))

__device__ __forceinline__ void ldsm4(uint32_t addr, uint32_t& r0, uint32_t& r1,
                                      uint32_t& r2, uint32_t& r3) {
    asm volatile("ldmatrix.sync.aligned.m8n8.x4.shared.b16 {%0,%1,%2,%3}, [%4];"
                 : "=r"(r0), "=r"(r1), "=r"(r2), "=r"(r3) : "r"(addr));
}
__device__ __forceinline__ void cpasync16(uint32_t saddr, const void* g) {
    asm volatile("cp.async.cg.shared.global [%0], [%1], 16;" :: "r"(saddr), "l"(g));
}
#define CP_COMMIT() asm volatile("cp.async.commit_group;" ::: "memory")
#define CP_WAIT0()  asm volatile("cp.async.wait_group 0;" ::: "memory")
#define CP_WAIT1()  asm volatile("cp.async.wait_group 1;" ::: "memory")

// ---------------- small elementwise kernels ----------------
__global__ void bias_concat_kernel(const float* bq, const float* bk, const float* bv) {
    int c = blockIdx.x * 768 + threadIdx.x;
    const float* s = (blockIdx.x == 0) ? bq : (blockIdx.x == 1) ? bk : bv;
    g_biasqkv[c] = s[threadIdx.x];
}

__global__ void conv_kernel(const float* __restrict__ src, bf16* __restrict__ hi,
                            bf16* __restrict__ lo, int n) {
    int i = blockIdx.x * 256 + threadIdx.x;
    if (i < n) {
        float v = src[i];
        bf16 h = __float2bfloat16(v);
        hi[i] = h;
        lo[i] = __float2bfloat16(v - __bfloat162float(h));
    }
}

__global__ void convT_kernel(const float* __restrict__ src, bf16* __restrict__ hi,
                             bf16* __restrict__ lo) {
    __shared__ float tile[32][33];
    int c0 = blockIdx.x * 32, r0 = blockIdx.y * 32;
    int tx = threadIdx.x, ty = threadIdx.y;
#pragma unroll
    for (int i = 0; i < 4; ++i)
        tile[ty + i * 8][tx] = src[(size_t)(r0 + ty + i * 8) * DIM_ + c0 + tx];
    __syncthreads();
#pragma unroll
    for (int i = 0; i < 4; ++i) {
        float v = tile[tx][ty + i * 8];
        size_t o = (size_t)(c0 + ty + i * 8) * DIM_ + r0 + tx;
        bf16 h = __float2bfloat16(v);
        hi[o] = h;
        lo[o] = __float2bfloat16(v - __bfloat162float(h));
    }
}

// ---------------- 128x128 warp-MMA GEMM, cp.async double-buffered ---------
// C[M][N] = A[M][K] @ B[N][K]^T ; both K-major, K % 64 == 0.
// 256 threads = 8 warps in 4(m) x 2(n); warp tile 32x64.
// Stage layout (bytes): AsH 0, AsL 18432, BsH 36864, BsL 55296; stage 73728.
#define GSTG 73728
__global__ __launch_bounds__(256)
void gemm128_kernel(const bf16* __restrict__ Ah, const bf16* __restrict__ Al, int lda,
                    const bf16* __restrict__ Bh, const bf16* __restrict__ Bl, int ldb,
                    float* __restrict__ Cf, bf16* __restrict__ Chi, bf16* __restrict__ Clo,
                    int ldc, int K, const float* __restrict__ bias) {
    extern __shared__ char smem[];
    uint32_t sb = smem_u32(smem);
    int tid = threadIdx.x, lane = tid & 31, wid = tid >> 5;
    int g = lane >> 2, tig = lane & 3;
    int wm = (wid >> 1) * 32, wn = (wid & 1) * 64;
    int m0 = blockIdx.y * 128, n0 = blockIdx.x * 128;
    int r16 = lane & 15, koff = (lane >> 4) * 8;

    float acc[2][8][4];
#pragma unroll
    for (int mt = 0; mt < 2; ++mt)
#pragma unroll
        for (int nt = 0; nt < 8; ++nt)
#pragma unroll
            for (int i = 0; i < 4; ++i) acc[mt][nt][i] = 0.f;

    int lrow = tid >> 3, lseg = (tid & 7) * 8;   // 128 rows x 8 segs, 2 rows/thread-step
    auto load_chunk = [&](int kc, int s) {
        uint32_t st = sb + s * GSTG;
#pragma unroll
        for (int it = 0; it < 4; ++it) {
            int row = lrow + it * 32;
            uint32_t so = row * 144 + lseg * 2;
            size_t ga = (size_t)(m0 + row) * lda + kc + lseg;
            size_t gb = (size_t)(n0 + row) * ldb + kc + lseg;
            cpasync16(st +         so, Ah + ga);
            cpasync16(st + 18432 + so, Al + ga);
            cpasync16(st + 36864 + so, Bh + gb);
            cpasync16(st + 55296 + so, Bl + gb);
        }
    };

    int nch = K / 64;
    load_chunk(0, 0);
    CP_COMMIT();
    for (int c = 0; c < nch; ++c) {
        int s = c & 1;
        if (c + 1 < nch) { load_chunk((c + 1) * 64, s ^ 1); CP_COMMIT(); CP_WAIT1(); }
        else CP_WAIT0();
        __syncthreads();
        uint32_t st = sb + s * GSTG;
#pragma unroll
        for (int ks = 0; ks < 4; ++ks) {
            uint32_t ah[2][4], al[2][4];
#pragma unroll
            for (int mt = 0; mt < 2; ++mt) {
                uint32_t aadr = st + (wm + mt * 16 + r16) * 144 + (ks * 16 + koff) * 2;
                ldsm4(aadr,         ah[mt][0], ah[mt][1], ah[mt][2], ah[mt][3]);
                ldsm4(aadr + 18432, al[mt][0], al[mt][1], al[mt][2], al[mt][3]);
            }
#pragma unroll
            for (int ntp = 0; ntp < 4; ++ntp) {
                uint32_t badr = st + 36864 + (wn + ntp * 16 + r16) * 144 + (ks * 16 + koff) * 2;
                uint32_t bh4[4], bl4[4];
                ldsm4(badr,         bh4[0], bh4[1], bh4[2], bh4[3]);
                ldsm4(badr + 18432, bl4[0], bl4[1], bl4[2], bl4[3]);
#pragma unroll
                for (int half = 0; half < 2; ++half) {
                    int nt = 2 * ntp + half;
                    uint32_t bh0 = bh4[half], bh1 = bh4[half + 2];
                    uint32_t bl0 = bl4[half], bl1 = bl4[half + 2];
#pragma unroll
                    for (int mt = 0; mt < 2; ++mt) {
                        MMA16(acc[mt][nt], ah[mt], bh0, bh1);
                        MMA16(acc[mt][nt], ah[mt], bl0, bl1);
                        MMA16(acc[mt][nt], al[mt], bh0, bh1);
                    }
                }
            }
        }
        __syncthreads();
    }
    // epilogue
#pragma unroll
    for (int mt = 0; mt < 2; ++mt)
#pragma unroll
        for (int nt = 0; nt < 8; ++nt) {
            int row = m0 + wm + mt * 16 + g;
            int col = n0 + wn + nt * 8 + 2 * tig;
            float v0 = acc[mt][nt][0], v1 = acc[mt][nt][1];
            float v2 = acc[mt][nt][2], v3 = acc[mt][nt][3];
            if (bias) {
                float b0v = bias[col], b1v = bias[col + 1];
                v0 += b0v; v1 += b1v; v2 += b0v; v3 += b1v;
            }
            if (Cf) {
                *(float2*)(Cf + (size_t)row * ldc + col)       = make_float2(v0, v1);
                *(float2*)(Cf + (size_t)(row + 8) * ldc + col) = make_float2(v2, v3);
            }
            if (Chi) {
                uint32_t h01 = packhi2(v0, v1), h23 = packhi2(v2, v3);
                *(uint32_t*)(Chi + (size_t)row * ldc + col)       = h01;
                *(uint32_t*)(Chi + (size_t)(row + 8) * ldc + col) = h23;
                *(uint32_t*)(Clo + (size_t)row * ldc + col)       = packlo2(v0, v1, h01);
                *(uint32_t*)(Clo + (size_t)(row + 8) * ldc + col) = packlo2(v2, v3, h23);
            }
        }
}

// ---------------- area pooling (integral image) -> bf16 hi/lo ------------
__global__ __launch_bounds__(256)
void pool_kernel() {
    int bh = blockIdx.x;
    int b = bh / HEADS_, h = bh % HEADS_;
    extern __shared__ float sat[];  // [64][289]
    int t = threadIdx.x;
    const int cnts[9] = {256, 240, 224, 240, 225, 210, 224, 210, 196};

    for (int pass = 0; pass < 2; ++pass) {
        const float* base = g_qkvh_f + (size_t)(b * N_) * K3 + (pass ? 2 * DIM_ : DIM_) + h * DHEAD_;
        for (int it = 0; it < 4; ++it) {
            int task = t + it * 256;
            int ch = task & 63, row = task >> 6;
            if (row == 0)
                for (int x = 0; x < 17; ++x) sat[ch * 289 + x] = 0.f;
            float acc = 0.f;
            sat[ch * 289 + (row + 1) * 17] = 0.f;
            for (int x = 0; x < 16; ++x) {
                acc += base[(size_t)(row * 16 + x) * K3 + ch];
                sat[ch * 289 + (row + 1) * 17 + x + 1] = acc;
            }
        }
        __syncthreads();
        for (int it = 0; it < 4; ++it) {
            int task = t + it * 256;
            int ch = task >> 4, col = (task & 15) + 1;
            float acc = 0.f;
            for (int y = 1; y <= 16; ++y) {
                acc += sat[ch * 289 + y * 17 + col];
                sat[ch * 289 + y * 17 + col] = acc;
            }
        }
        __syncthreads();
        for (int m = t; m < MPAD; m += 256) {
            float scale = 0.f;
            int y0 = 0, x0 = 0, ah = 1, aw = 1;
            bool valid = (m < MAREA);
            if (valid) {
                int rem = m, seg = 0;
                while (rem >= cnts[seg]) { rem -= cnts[seg]; ++seg; }
                ah = seg / 3 + 1; aw = seg % 3 + 1;
                int w = 17 - aw;
                y0 = rem / w; x0 = rem % w;
                scale = (pass == 0) ? 1.f / (float)(ah * aw) : 1.f;
            }
            for (int c = 0; c < 64; ++c) {
                float s = 0.f;
                if (valid) {
                    s = sat[c * 289 + (y0 + ah) * 17 + x0 + aw] - sat[c * 289 + y0 * 17 + x0 + aw]
                      - sat[c * 289 + (y0 + ah) * 17 + x0]      + sat[c * 289 + y0 * 17 + x0];
                    s *= scale;
                }
                bf16 hi = __float2bfloat16(s);
                bf16 lo = __float2bfloat16(s - __bfloat162float(hi));
                if (pass == 0) {
                    size_t o = ((size_t)bh * MPAD + m) * DHEAD_ + c;
                    g_ka_hi[o] = hi; g_ka_lo[o] = lo;
                } else {
                    size_t o = ((size_t)bh * DHEAD_ + c) * MPAD + m;
                    g_vt_hi[o] = hi; g_vt_lo[o] = lo;
                }
            }
        }
        __syncthreads();
    }
}

// ---------------- fused warp-MMA attention, cp.async double-buffered ------
// grid (BH_, 2): CTA = (bh, 128 queries). 8 warps: 4(m) x 2(n).
// smem: Q (Qh 0, Ql 18432) = 36864; stages at 36864:
//   per stage {Kh 0, Kl 18432, Vh 36864, Vl 54272}, stage = 71680. Total 180224.
#define ASTG 71680
#define AQOF 36864
__global__ __launch_bounds__(256)
void attn_kernel() {
    extern __shared__ char smem[];
    uint32_t sb = smem_u32(smem);
    int tid = threadIdx.x, lane = tid & 31, wid = tid >> 5;
    int g = lane >> 2, tig = lane & 3;
    int wm = (wid >> 1) * 32, wn = wid & 1;
    int bh = blockIdx.x, q0 = blockIdx.y * 128;
    int b = bh / HEADS_, h = bh % HEADS_;
    int r16 = lane & 15, koff = (lane >> 4) * 8;

    // Q tile (persists at smem base)
    bf16* Qs = (bf16*)smem;
#pragma unroll
    for (int it = 0; it < 4; ++it) {
        int idx = tid + it * 256;
        int row = idx >> 3, seg = (idx & 7) * 8;
        size_t src = (size_t)(b * N_ + q0 + row) * K3 + h * 64 + seg;
        *(uint4*)(Qs + row * 72 + seg)        = *(const uint4*)(g_qkvh_hi + src);
        *(uint4*)(Qs + 9216 + row * 72 + seg) = *(const uint4*)(g_qkvh_lo + src);
    }

    const bf16* kaH = g_ka_hi + (size_t)bh * MPAD * 64;
    const bf16* kaL = g_ka_lo + (size_t)bh * MPAD * 64;
    const bf16* vtH = g_vt_hi + (size_t)bh * 64 * MPAD;
    const bf16* vtL = g_vt_lo + (size_t)bh * 64 * MPAD;

    int lrow = tid >> 3, lseg = (tid & 7) * 8;      // K: 128 x 8 segs
    int vlrow = tid >> 4, vlseg = (tid & 15) * 8;   // V: 64 x 16 segs
    auto load_tile = [&](int t, int s) {
        uint32_t st = sb + AQOF + s * ASTG;
#pragma unroll
        for (int it = 0; it < 4; ++it) {
            int row = lrow + it * 32;
            uint32_t so = row * 144 + lseg * 2;
            size_t gk = (size_t)(t * 128 + row) * 64 + lseg;
            cpasync16(st +         so, kaH + gk);
            cpasync16(st + 18432 + so, kaL + gk);
            int vrow = vlrow + it * 16;
            uint32_t vo = vrow * 272 + vlseg * 2;
            size_t gv = (size_t)vrow * MPAD + t * 128 + vlseg;
            cpasync16(st + 36864 + vo, vtH + gv);
            cpasync16(st + 54272 + vo, vtL + gv);
        }
    };

    float accO[2][8][4];
#pragma unroll
    for (int mt = 0; mt < 2; ++mt)
#pragma unroll
        for (int nt = 0; nt < 8; ++nt)
#pragma unroll
            for (int i = 0; i < 4; ++i) accO[mt][nt][i] = 0.f;
    float lsum[2][2] = {{0.f, 0.f}, {0.f, 0.f}};

    load_tile(0, 0);
    CP_COMMIT();
    for (int t = 0; t < MPAD / 128; ++t) {
        int s = t & 1;
        if (t + 1 < MPAD / 128) { load_tile(t + 1, s ^ 1); CP_COMMIT(); CP_WAIT1(); }
        else CP_WAIT0();
        __syncthreads();
        uint32_t st = sb + AQOF + s * ASTG;

        // ---- QK ----
        float sc[2][8][4];
#pragma unroll
        for (int mt = 0; mt < 2; ++mt)
#pragma unroll
            for (int nt = 0; nt < 8; ++nt)
#pragma unroll
                for (int i = 0; i < 4; ++i) sc[mt][nt][i] = 0.f;
#pragma unroll
        for (int ks = 0; ks < 4; ++ks) {
            uint32_t qh[2][4], ql[2][4];
#pragma unroll
            for (int mt = 0; mt < 2; ++mt) {
                uint32_t qadr = sb + (wm + mt * 16 + r16) * 144 + (ks * 16 + koff) * 2;
                ldsm4(qadr,         qh[mt][0], qh[mt][1], qh[mt][2], qh[mt][3]);
                ldsm4(qadr + 18432, ql[mt][0], ql[mt][1], ql[mt][2], ql[mt][3]);
            }
#pragma unroll
            for (int ntp = 0; ntp < 4; ++ntp) {
                uint32_t kadr = st + (wn * 64 + ntp * 16 + r16) * 144 + (ks * 16 + koff) * 2;
                uint32_t kh4[4], kl4[4];
                ldsm4(kadr,         kh4[0], kh4[1], kh4[2], kh4[3]);
                ldsm4(kadr + 18432, kl4[0], kl4[1], kl4[2], kl4[3]);
#pragma unroll
                for (int half = 0; half < 2; ++half) {
                    int nt = 2 * ntp + half;
                    uint32_t b0h = kh4[half], b1h = kh4[half + 2];
                    uint32_t b0l = kl4[half], b1l = kl4[half + 2];
#pragma unroll
                    for (int mt = 0; mt < 2; ++mt) {
                        MMA16(sc[mt][nt], qh[mt], b0h, b1h);
                        MMA16(sc[mt][nt], qh[mt], b0l, b1l);
                        MMA16(sc[mt][nt], ql[mt], b0h, b1h);
                    }
                }
            }
        }

        // ---- softmax (no max subtraction; logits are small) ----
#pragma unroll
        for (int mt = 0; mt < 2; ++mt)
#pragma unroll
            for (int nt = 0; nt < 8; ++nt) {
                int cb = t * 128 + wn * 64 + nt * 8 + 2 * tig;
                float p0 = (cb     < MAREA) ? __expf(sc[mt][nt][0]) : 0.f;
                float p1 = (cb + 1 < MAREA) ? __expf(sc[mt][nt][1]) : 0.f;
                float p2 = (cb     < MAREA) ? __expf(sc[mt][nt][2]) : 0.f;
                float p3 = (cb + 1 < MAREA) ? __expf(sc[mt][nt][3]) : 0.f;
                sc[mt][nt][0] = p0; sc[mt][nt][1] = p1;
                sc[mt][nt][2] = p2; sc[mt][nt][3] = p3;
                lsum[mt][0] += p0 + p1;
                lsum[mt][1] += p2 + p3;
            }

        // ---- PV: accO += P @ V^T ----
#pragma unroll
        for (int kk = 0; kk < 4; ++kk) {
            uint32_t pah[2][4], pal[2][4];
#pragma unroll
            for (int mt = 0; mt < 2; ++mt) {
                pah[mt][0] = packhi2(sc[mt][2 * kk][0],     sc[mt][2 * kk][1]);
                pah[mt][1] = packhi2(sc[mt][2 * kk][2],     sc[mt][2 * kk][3]);
                pah[mt][2] = packhi2(sc[mt][2 * kk + 1][0], sc[mt][2 * kk + 1][1]);
                pah[mt][3] = packhi2(sc[mt][2 * kk + 1][2], sc[mt][2 * kk + 1][3]);
                pal[mt][0] = packlo2(sc[mt][2 * kk][0],     sc[mt][2 * kk][1],     pah[mt][0]);
                pal[mt][1] = packlo2(sc[mt][2 * kk][2],     sc[mt][2 * kk][3],     pah[mt][1]);
                pal[mt][2] = packlo2(sc[mt][2 * kk + 1][0], sc[mt][2 * kk + 1][1], pah[mt][2]);
                pal[mt][3] = packlo2(sc[mt][2 * kk + 1][2], sc[mt][2 * kk + 1][3], pah[mt][3]);
            }
#pragma unroll
            for (int ntp = 0; ntp < 4; ++ntp) {
                uint32_t vadr = st + 36864 + (ntp * 16 + r16) * 272
                              + (wn * 64 + kk * 16 + koff) * 2;
                uint32_t vh4[4], vl4[4];
                ldsm4(vadr,         vh4[0], vh4[1], vh4[2], vh4[3]);
                ldsm4(vadr + 17408, vl4[0], vl4[1], vl4[2], vl4[3]);
#pragma unroll
                for (int half = 0; half < 2; ++half) {
                    int nt = 2 * ntp + half;
                    uint32_t b0h = vh4[half], b1h = vh4[half + 2];
                    uint32_t b0l = vl4[half], b1l = vl4[half + 2];
#pragma unroll
                    for (int mt = 0; mt < 2; ++mt) {
                        MMA16(accO[mt][nt], pah[mt], b0h, b1h);
                        MMA16(accO[mt][nt], pah[mt], b0l, b1l);
                        MMA16(accO[mt][nt], pal[mt], b0h, b1h);
                    }
                }
            }
        }
        __syncthreads();
    }

    // ---- reduce l over tig ----
#pragma unroll
    for (int mt = 0; mt < 2; ++mt)
#pragma unroll
        for (int r = 0; r < 2; ++r) {
            lsum[mt][r] += __shfl_xor_sync(0xFFFFFFFF, lsum[mt][r], 1);
            lsum[mt][r] += __shfl_xor_sync(0xFFFFFFFF, lsum[mt][r], 2);
        }

    __syncthreads();
    float* Ored = (float*)(smem + AQOF);            // 32KB scratch (stage0 K region)
    float* lred = (float*)(smem + AQOF + ASTG);     // stage1 base
    if (wn == 1) {
#pragma unroll
        for (int mt = 0; mt < 2; ++mt) {
            int r0 = wm + mt * 16 + g;
#pragma unroll
            for (int nt = 0; nt < 8; ++nt) {
                int cc = nt * 8 + 2 * tig;
                Ored[r0 * 64 + cc]           = accO[mt][nt][0];
                Ored[r0 * 64 + cc + 1]       = accO[mt][nt][1];
                Ored[(r0 + 8) * 64 + cc]     = accO[mt][nt][2];
                Ored[(r0 + 8) * 64 + cc + 1] = accO[mt][nt][3];
            }
            if (tig == 0) {
                lred[r0]     = lsum[mt][0];
                lred[r0 + 8] = lsum[mt][1];
            }
        }
    }
    __syncthreads();
    if (wn == 0) {
#pragma unroll
        for (int mt = 0; mt < 2; ++mt) {
            int r0 = wm + mt * 16 + g;
            float inv0 = 1.f / (lsum[mt][0] + lred[r0]);
            float inv1 = 1.f / (lsum[mt][1] + lred[r0 + 8]);
            size_t orow0 = (size_t)(b * N_ + q0 + r0) * DIM_ + h * 64;
            size_t orow1 = (size_t)(b * N_ + q0 + r0 + 8) * DIM_ + h * 64;
#pragma unroll
            for (int nt = 0; nt < 8; ++nt) {
                int cc = nt * 8 + 2 * tig;
                float o0 = (accO[mt][nt][0] + Ored[r0 * 64 + cc])           * inv0;
                float o1 = (accO[mt][nt][1] + Ored[r0 * 64 + cc + 1])       * inv0;
                float o2 = (accO[mt][nt][2] + Ored[(r0 + 8) * 64 + cc])     * inv1;
                float o3 = (accO[mt][nt][3] + Ored[(r0 + 8) * 64 + cc + 1]) * inv1;
                uint32_t h01 = packhi2(o0, o1), h23 = packhi2(o2, o3);
                *(uint32_t*)(g_attn_hi + orow0 + cc) = h01;
                *(uint32_t*)(g_attn_hi + orow1 + cc) = h23;
                *(uint32_t*)(g_attn_lo + orow0 + cc) = packlo2(o0, o1, h01);
                *(uint32_t*)(g_attn_lo + orow1 + cc) = packlo2(o2, o3, h23);
            }
        }
    }
}

// ---------------- launch ---------------------------------------------------
extern "C" void kernel_launch(void* const* d_in, const int* in_sizes, int n_in,
                              void* d_out, int out_size) {
    const float* x     = (const float*)d_in[0];
    const float* w_qkv = (const float*)d_in[1];
    const float* w_q   = (const float*)d_in[2];
    const float* b_q   = (const float*)d_in[3];
    const float* w_k   = (const float*)d_in[4];
    const float* b_k   = (const float*)d_in[5];
    const float* w_v   = (const float*)d_in[6];
    const float* b_v   = (const float*)d_in[7];
    const float* w_o   = (const float*)d_in[8];
    const float* b_o   = (const float*)d_in[9];
    float* out = (float*)d_out;

    cudaFuncSetAttribute(gemm128_kernel, cudaFuncAttributeMaxDynamicSharedMemorySize, 2 * GSTG);
    cudaFuncSetAttribute(attn_kernel,    cudaFuncAttributeMaxDynamicSharedMemorySize, AQOF + 2 * ASTG);
    cudaFuncSetAttribute(pool_kernel,    cudaFuncAttributeMaxDynamicSharedMemorySize, 73984);

    bf16 *x_hi, *x_lo, *wqkv_hi, *wqkv_lo, *wT_hi, *wT_lo, *woT_hi, *woT_lo;
    bf16 *weffT_hi, *weffT_lo, *qkvh_hi, *qkvh_lo, *attn_hi, *attn_lo;
    float *qkvh_f, *biasqkv;
    cudaGetSymbolAddress((void**)&x_hi, g_x_hi);       cudaGetSymbolAddress((void**)&x_lo, g_x_lo);
    cudaGetSymbolAddress((void**)&wqkv_hi, g_wqkv_hi); cudaGetSymbolAddress((void**)&wqkv_lo, g_wqkv_lo);
    cudaGetSymbolAddress((void**)&wT_hi, g_wT_hi);     cudaGetSymbolAddress((void**)&wT_lo, g_wT_lo);
    cudaGetSymbolAddress((void**)&woT_hi, g_woT_hi);   cudaGetSymbolAddress((void**)&woT_lo, g_woT_lo);
    cudaGetSymbolAddress((void**)&weffT_hi, g_weffT_hi); cudaGetSymbolAddress((void**)&weffT_lo, g_weffT_lo);
    cudaGetSymbolAddress((void**)&qkvh_f, g_qkvh_f);
    cudaGetSymbolAddress((void**)&qkvh_hi, g_qkvh_hi); cudaGetSymbolAddress((void**)&qkvh_lo, g_qkvh_lo);
    cudaGetSymbolAddress((void**)&attn_hi, g_attn_hi); cudaGetSymbolAddress((void**)&attn_lo, g_attn_lo);
    cudaGetSymbolAddress((void**)&biasqkv, g_biasqkv);

    // 1. bias concat + conversions
    bias_concat_kernel<<<3, 768>>>(b_q, b_k, b_v);
    conv_kernel<<<(ROWS_ * DIM_ + 255) / 256, 256>>>(x, x_hi, x_lo, ROWS_ * DIM_);
    conv_kernel<<<(DIM_ * K3 + 255) / 256, 256>>>(w_qkv, wqkv_hi, wqkv_lo, DIM_ * K3);
    {
        dim3 g(24, 24), blk(32, 8);
        convT_kernel<<<g, blk>>>(w_q, wT_hi,                   wT_lo);
        convT_kernel<<<g, blk>>>(w_k, wT_hi + DIM_ * DIM_,     wT_lo + DIM_ * DIM_);
        convT_kernel<<<g, blk>>>(w_v, wT_hi + 2 * DIM_ * DIM_, wT_lo + 2 * DIM_ * DIM_);
        convT_kernel<<<g, blk>>>(w_o, woT_hi, woT_lo);
    }

    // 2. compose W_eff^T[seg] = w_seg^T @ w_qkv_seg^T  (768x768, K=768)
    for (int seg = 0; seg < 3; ++seg) {
        dim3 g(6, 6);
        gemm128_kernel<<<g, 256, 2 * GSTG>>>(
            wT_hi + (size_t)seg * DIM_ * DIM_, wT_lo + (size_t)seg * DIM_ * DIM_, DIM_,
            wqkv_hi + seg * DIM_, wqkv_lo + seg * DIM_, K3,
            nullptr,
            weffT_hi + (size_t)seg * DIM_ * DIM_, weffT_lo + (size_t)seg * DIM_ * DIM_,
            DIM_, DIM_, nullptr);
    }

    // 3. qh|kh|vh = x @ W_eff + bias  ([4096,768] @ [768,2304])
    {
        dim3 g(K3 / 128, ROWS_ / 128);
        gemm128_kernel<<<g, 256, 2 * GSTG>>>(x_hi, x_lo, DIM_, weffT_hi, weffT_lo, DIM_,
                                             qkvh_f, qkvh_hi, qkvh_lo, K3, DIM_, biasqkv);
    }

    // 4. area pooling -> K means + V^T sums (bf16 hi/lo)
    pool_kernel<<<BH_, 256, 73984>>>();

    // 5. fused warp-MMA attention
    {
        dim3 g(BH_, 2);
        attn_kernel<<<g, 256, AQOF + 2 * ASTG>>>();
    }

    // 6. out = attn @ w_o + b_o
    {
        dim3 g(DIM_ / 128, ROWS_ / 128);
        gemm128_kernel<<<g, 256, 2 * GSTG>>>(attn_hi, attn_lo, DIM_, woT_hi, woT_lo, DIM_,
                                             out, nullptr, nullptr, DIM_, DIM_, b_o);
    }
}

// round 7
// speedup vs baseline: 1.6330x; 1.0609x over previous
#include <cuda_runtime.h>
#include <cuda_bf16.h>
#include <cstdint>

#define B_     16
#define N_     256
#define DIM_   768
#define HEADS_ 12
#define DHEAD_ 64
#define BH_    192
#define MAREA  2025
#define MPAD   2048
#define ROWS_  4096
#define K3     2304

typedef __nv_bfloat16 bf16;

// ---------------- device global scratch ----------------
__device__ float g_biasqkv[K3];
__device__ float g_dummyv;
__device__ bf16  g_x_hi[ROWS_*DIM_],   g_x_lo[ROWS_*DIM_];
__device__ bf16  g_wqkv_hi[DIM_*K3],   g_wqkv_lo[DIM_*K3];
__device__ bf16  g_wT_hi[3*DIM_*DIM_], g_wT_lo[3*DIM_*DIM_];
__device__ bf16  g_woT_hi[DIM_*DIM_],  g_woT_lo[DIM_*DIM_];
__device__ bf16  g_weffT_hi[K3*DIM_],  g_weffT_lo[K3*DIM_];
__device__ float g_qkvh_f[(size_t)ROWS_*K3];
__device__ bf16  g_qkvh_hi[(size_t)ROWS_*K3], g_qkvh_lo[(size_t)ROWS_*K3];
__device__ bf16  g_ka_hi[(size_t)BH_*MPAD*DHEAD_], g_ka_lo[(size_t)BH_*MPAD*DHEAD_];
__device__ bf16  g_vt_hi[(size_t)BH_*DHEAD_*MPAD], g_vt_lo[(size_t)BH_*DHEAD_*MPAD];
__device__ bf16  g_attn_hi[(size_t)ROWS_*DIM_],    g_attn_lo[(size_t)ROWS_*DIM_];

// ---------------- helpers ----------------
__device__ __forceinline__ uint32_t smem_u32(const void* p) {
    uint32_t a;
    asm("{ .reg .u64 t; cvta.to.shared.u64 t, %1; cvt.u32.u64 %0, t; }" : "=r"(a) : "l"(p));
    return a;
}
__device__ __forceinline__ uint32_t packhi2(float x, float y) {
    __nv_bfloat162 t = __floats2bfloat162_rn(x, y);
    return *(uint32_t*)&t;
}
__device__ __forceinline__ uint32_t packlo2(float x, float y, uint32_t hp) {
    __nv_bfloat162 h = *(__nv_bfloat162*)&hp;
    __nv_bfloat162 t = __floats2bfloat162_rn(x - __bfloat162float(h.x),
                                             y - __bfloat162float(h.y));
    return *(uint32_t*)&t;
}

#define MMA16(d, a, b0, b1) \
    asm volatile("mma.sync.aligned.m16n8k16.row.col.f32.bf16.bf16.f32 " \
        "{%0,%1,%2,%3}, {%4,%5,%6,%7}, {%8,%9}, {%0,%1,%2,%3};" \
        : "+f"((d)[0]), "+f"((d)[1]), "+f"((d)[2]), "+f"((d)[3]) \
        : "r"((a)[0]), "r"((a)[1]), "r"((a)[2]), "r"((a)[3]), "r"(b0), "r"(b1))

__device__ __forceinline__ void ldsm4(uint32_t addr, uint32_t& r0, uint32_t& r1,
                                      uint32_t& r2, uint32_t& r3) {
    asm volatile("ldmatrix.sync.aligned.m8n8.x4.shared.b16 {%0,%1,%2,%3}, [%4];"
                 : "=r"(r0), "=r"(r1), "=r"(r2), "=r"(r3) : "r"(addr));
}
__device__ __forceinline__ void cpasync16(uint32_t saddr, const void* g) {
    asm volatile("cp.async.cg.shared.global [%0], [%1], 16;" :: "r"(saddr), "l"(g));
}
#define CP_COMMIT() asm volatile("cp.async.commit_group;" ::: "memory")
#define CP_WAIT0()  asm volatile("cp.async.wait_group 0;" ::: "memory")
#define CP_WAIT1()  asm volatile("cp.async.wait_group 1;" ::: "memory")

// ---------------- fused prep kernel (bias + conversions + transposes) -----
#define NB_CONVX 12288
#define NB_CONVW 6912
#define NB_CONVT 2304
__global__ __launch_bounds__(256)
void prep_kernel(const float* __restrict__ x, const float* __restrict__ w_qkv,
                 const float* __restrict__ w_q, const float* __restrict__ w_k,
                 const float* __restrict__ w_v, const float* __restrict__ w_o,
                 const float* __restrict__ bq, const float* __restrict__ bk,
                 const float* __restrict__ bv) {
    __shared__ float tile[32][33];
    int bx = blockIdx.x, t = threadIdx.x;
    if (bx < NB_CONVX) {
        int i = bx * 256 + t;
        float v = x[i];
        bf16 h = __float2bfloat16(v);
        g_x_hi[i] = h;
        g_x_lo[i] = __float2bfloat16(v - __bfloat162float(h));
    } else if (bx < NB_CONVX + NB_CONVW) {
        int i = (bx - NB_CONVX) * 256 + t;
        float v = w_qkv[i];
        bf16 h = __float2bfloat16(v);
        g_wqkv_hi[i] = h;
        g_wqkv_lo[i] = __float2bfloat16(v - __bfloat162float(h));
    } else if (bx < NB_CONVX + NB_CONVW + NB_CONVT) {
        int id = bx - (NB_CONVX + NB_CONVW);
        int seg = id / 576, rem = id % 576;
        int c0 = (rem % 24) * 32, r0 = (rem / 24) * 32;
        const float* src = (seg == 0) ? w_q : (seg == 1) ? w_k : (seg == 2) ? w_v : w_o;
        bf16* hi = (seg < 3) ? (g_wT_hi + (size_t)seg * DIM_ * DIM_) : g_woT_hi;
        bf16* lo = (seg < 3) ? (g_wT_lo + (size_t)seg * DIM_ * DIM_) : g_woT_lo;
        int tx = t & 31, ty = t >> 5;
#pragma unroll
        for (int i = 0; i < 4; ++i)
            tile[ty + i * 8][tx] = src[(size_t)(r0 + ty + i * 8) * DIM_ + c0 + tx];
        __syncthreads();
#pragma unroll
        for (int i = 0; i < 4; ++i) {
            float v = tile[tx][ty + i * 8];
            size_t o = (size_t)(c0 + ty + i * 8) * DIM_ + r0 + tx;
            bf16 h = __float2bfloat16(v);
            hi[o] = h;
            lo[o] = __float2bfloat16(v - __bfloat162float(h));
        }
    } else {
        int idx = (bx - (NB_CONVX + NB_CONVW + NB_CONVT)) * 256 + t;
        int seg = idx / 768;
        const float* s = (seg == 0) ? bq : (seg == 1) ? bk : bv;
        g_biasqkv[idx] = s[idx % 768];
    }
}

__global__ void dummy_kernel() {
    if (threadIdx.x == 0) g_dummyv = 1.f;
}

// ---------------- 128x128 warp-MMA GEMM, BK=32, 2 CTAs/SM -----------------
// C[M][N] = A[M][K] @ B[N][K]^T ; both K-major, K % 32 == 0.
// Stage (bytes, 80B rows): AsH 0, AsL 10240, BsH 20480, BsL 30720; GSTG 40960.
#define GSTG 40960
__global__ __launch_bounds__(256, 2)
void gemm128_kernel(const bf16* __restrict__ Ah, const bf16* __restrict__ Al, int lda,
                    const bf16* __restrict__ Bh, const bf16* __restrict__ Bl, int ldb,
                    float* __restrict__ Cf, bf16* __restrict__ Chi, bf16* __restrict__ Clo,
                    int ldc, int K, const float* __restrict__ bias,
                    int sAz, int sBz, int sCz) {
    extern __shared__ char smem[];
    uint32_t sb = smem_u32(smem);
    int z = blockIdx.z;
    Ah += (size_t)z * sAz; Al += (size_t)z * sAz;
    Bh += (size_t)z * sBz; Bl += (size_t)z * sBz;
    if (Cf)  Cf  += (size_t)z * sCz;
    if (Chi) { Chi += (size_t)z * sCz; Clo += (size_t)z * sCz; }

    int tid = threadIdx.x, lane = tid & 31, wid = tid >> 5;
    int g = lane >> 2, tig = lane & 3;
    int wm = (wid >> 1) * 32, wn = (wid & 1) * 64;
    int m0 = blockIdx.y * 128, n0 = blockIdx.x * 128;
    int r16 = lane & 15, koff = (lane >> 4) * 8;

    float acc[2][8][4];
#pragma unroll
    for (int mt = 0; mt < 2; ++mt)
#pragma unroll
        for (int nt = 0; nt < 8; ++nt)
#pragma unroll
            for (int i = 0; i < 4; ++i) acc[mt][nt][i] = 0.f;

    // 128 rows x 32 bf16 = 512 16B-chunks per operand; 256 threads x 2 iters.
    auto load_chunk = [&](int kc, int s) {
        uint32_t st = sb + s * GSTG;
#pragma unroll
        for (int it = 0; it < 2; ++it) {
            int idx = tid + it * 256;
            int row = idx >> 2, seg8 = (idx & 3) * 8;
            uint32_t so = row * 80 + seg8 * 2;
            size_t ga = (size_t)(m0 + row) * lda + kc + seg8;
            size_t gb = (size_t)(n0 + row) * ldb + kc + seg8;
            cpasync16(st +         so, Ah + ga);
            cpasync16(st + 10240 + so, Al + ga);
            cpasync16(st + 20480 + so, Bh + gb);
            cpasync16(st + 30720 + so, Bl + gb);
        }
    };

    int nch = K / 32;
    load_chunk(0, 0);
    CP_COMMIT();
    for (int c = 0; c < nch; ++c) {
        int s = c & 1;
        if (c + 1 < nch) { load_chunk((c + 1) * 32, s ^ 1); CP_COMMIT(); CP_WAIT1(); }
        else CP_WAIT0();
        __syncthreads();
        uint32_t st = sb + s * GSTG;
#pragma unroll
        for (int ks = 0; ks < 2; ++ks) {
            uint32_t ah[2][4], al[2][4];
#pragma unroll
            for (int mt = 0; mt < 2; ++mt) {
                uint32_t aadr = st + (wm + mt * 16 + r16) * 80 + (ks * 16 + koff) * 2;
                ldsm4(aadr,         ah[mt][0], ah[mt][1], ah[mt][2], ah[mt][3]);
                ldsm4(aadr + 10240, al[mt][0], al[mt][1], al[mt][2], al[mt][3]);
            }
#pragma unroll
            for (int ntp = 0; ntp < 4; ++ntp) {
                uint32_t badr = st + 20480 + (wn + ntp * 16 + r16) * 80 + (ks * 16 + koff) * 2;
                uint32_t bh4[4], bl4[4];
                ldsm4(badr,         bh4[0], bh4[1], bh4[2], bh4[3]);
                ldsm4(badr + 10240, bl4[0], bl4[1], bl4[2], bl4[3]);
#pragma unroll
                for (int half = 0; half < 2; ++half) {
                    int nt = 2 * ntp + half;
                    uint32_t bh0 = bh4[half], bh1 = bh4[half + 2];
                    uint32_t bl0 = bl4[half], bl1 = bl4[half + 2];
#pragma unroll
                    for (int mt = 0; mt < 2; ++mt) {
                        MMA16(acc[mt][nt], ah[mt], bh0, bh1);
                        MMA16(acc[mt][nt], ah[mt], bl0, bl1);
                        MMA16(acc[mt][nt], al[mt], bh0, bh1);
                    }
                }
            }
        }
        __syncthreads();
    }
    // epilogue
#pragma unroll
    for (int mt = 0; mt < 2; ++mt)
#pragma unroll
        for (int nt = 0; nt < 8; ++nt) {
            int row = m0 + wm + mt * 16 + g;
            int col = n0 + wn + nt * 8 + 2 * tig;
            float v0 = acc[mt][nt][0], v1 = acc[mt][nt][1];
            float v2 = acc[mt][nt][2], v3 = acc[mt][nt][3];
            if (bias) {
                float b0v = bias[col], b1v = bias[col + 1];
                v0 += b0v; v1 += b1v; v2 += b0v; v3 += b1v;
            }
            if (Cf) {
                *(float2*)(Cf + (size_t)row * ldc + col)       = make_float2(v0, v1);
                *(float2*)(Cf + (size_t)(row + 8) * ldc + col) = make_float2(v2, v3);
            }
            if (Chi) {
                uint32_t h01 = packhi2(v0, v1), h23 = packhi2(v2, v3);
                *(uint32_t*)(Chi + (size_t)row * ldc + col)       = h01;
                *(uint32_t*)(Chi + (size_t)(row + 8) * ldc + col) = h23;
                *(uint32_t*)(Clo + (size_t)row * ldc + col)       = packlo2(v0, v1, h01);
                *(uint32_t*)(Clo + (size_t)(row + 8) * ldc + col) = packlo2(v2, v3, h23);
            }
        }
}

// ---------------- area pooling (integral image) -> bf16 hi/lo ------------
__global__ __launch_bounds__(256)
void pool_kernel() {
    int bh = blockIdx.x;
    int b = bh / HEADS_, h = bh % HEADS_;
    extern __shared__ float sat[];  // [64][289]
    int t = threadIdx.x;
    const int cnts[9] = {256, 240, 224, 240, 225, 210, 224, 210, 196};

    for (int pass = 0; pass < 2; ++pass) {
        const float* base = g_qkvh_f + (size_t)(b * N_) * K3 + (pass ? 2 * DIM_ : DIM_) + h * DHEAD_;
        for (int it = 0; it < 4; ++it) {
            int task = t + it * 256;
            int ch = task & 63, row = task >> 6;
            if (row == 0)
                for (int x = 0; x < 17; ++x) sat[ch * 289 + x] = 0.f;
            float acc = 0.f;
            sat[ch * 289 + (row + 1) * 17] = 0.f;
            for (int x = 0; x < 16; ++x) {
                acc += base[(size_t)(row * 16 + x) * K3 + ch];
                sat[ch * 289 + (row + 1) * 17 + x + 1] = acc;
            }
        }
        __syncthreads();
        for (int it = 0; it < 4; ++it) {
            int task = t + it * 256;
            int ch = task >> 4, col = (task & 15) + 1;
            float acc = 0.f;
            for (int y = 1; y <= 16; ++y) {
                acc += sat[ch * 289 + y * 17 + col];
                sat[ch * 289 + y * 17 + col] = acc;
            }
        }
        __syncthreads();
        for (int m = t; m < MPAD; m += 256) {
            float scale = 0.f;
            int y0 = 0, x0 = 0, ah = 1, aw = 1;
            bool valid = (m < MAREA);
            if (valid) {
                int rem = m, seg = 0;
                while (rem >= cnts[seg]) { rem -= cnts[seg]; ++seg; }
                ah = seg / 3 + 1; aw = seg % 3 + 1;
                int w = 17 - aw;
                y0 = rem / w; x0 = rem % w;
                scale = (pass == 0) ? 1.f / (float)(ah * aw) : 1.f;
            }
            for (int c = 0; c < 64; ++c) {
                float s = 0.f;
                if (valid) {
                    s = sat[c * 289 + (y0 + ah) * 17 + x0 + aw] - sat[c * 289 + y0 * 17 + x0 + aw]
                      - sat[c * 289 + (y0 + ah) * 17 + x0]      + sat[c * 289 + y0 * 17 + x0];
                    s *= scale;
                }
                bf16 hi = __float2bfloat16(s);
                bf16 lo = __float2bfloat16(s - __bfloat162float(hi));
                if (pass == 0) {
                    size_t o = ((size_t)bh * MPAD + m) * DHEAD_ + c;
                    g_ka_hi[o] = hi; g_ka_lo[o] = lo;
                } else {
                    size_t o = ((size_t)bh * DHEAD_ + c) * MPAD + m;
                    g_vt_hi[o] = hi; g_vt_lo[o] = lo;
                }
            }
        }
        __syncthreads();
    }
}

// ---------------- fused warp-MMA attention (unchanged, proven) ------------
#define ASTG 71680
#define AQOF 36864
__global__ __launch_bounds__(256)
void attn_kernel() {
    extern __shared__ char smem[];
    uint32_t sb = smem_u32(smem);
    int tid = threadIdx.x, lane = tid & 31, wid = tid >> 5;
    int g = lane >> 2, tig = lane & 3;
    int wm = (wid >> 1) * 32, wn = wid & 1;
    int bh = blockIdx.x, q0 = blockIdx.y * 128;
    int b = bh / HEADS_, h = bh % HEADS_;
    int r16 = lane & 15, koff = (lane >> 4) * 8;

    bf16* Qs = (bf16*)smem;
#pragma unroll
    for (int it = 0; it < 4; ++it) {
        int idx = tid + it * 256;
        int row = idx >> 3, seg = (idx & 7) * 8;
        size_t src = (size_t)(b * N_ + q0 + row) * K3 + h * 64 + seg;
        *(uint4*)(Qs + row * 72 + seg)        = *(const uint4*)(g_qkvh_hi + src);
        *(uint4*)(Qs + 9216 + row * 72 + seg) = *(const uint4*)(g_qkvh_lo + src);
    }

    const bf16* kaH = g_ka_hi + (size_t)bh * MPAD * 64;
    const bf16* kaL = g_ka_lo + (size_t)bh * MPAD * 64;
    const bf16* vtH = g_vt_hi + (size_t)bh * 64 * MPAD;
    const bf16* vtL = g_vt_lo + (size_t)bh * 64 * MPAD;

    int lrow = tid >> 3, lseg = (tid & 7) * 8;
    int vlrow = tid >> 4, vlseg = (tid & 15) * 8;
    auto load_tile = [&](int t, int s) {
        uint32_t st = sb + AQOF + s * ASTG;
#pragma unroll
        for (int it = 0; it < 4; ++it) {
            int row = lrow + it * 32;
            uint32_t so = row * 144 + lseg * 2;
            size_t gk = (size_t)(t * 128 + row) * 64 + lseg;
            cpasync16(st +         so, kaH + gk);
            cpasync16(st + 18432 + so, kaL + gk);
            int vrow = vlrow + it * 16;
            uint32_t vo = vrow * 272 + vlseg * 2;
            size_t gv = (size_t)vrow * MPAD + t * 128 + vlseg;
            cpasync16(st + 36864 + vo, vtH + gv);
            cpasync16(st + 54272 + vo, vtL + gv);
        }
    };

    float accO[2][8][4];
#pragma unroll
    for (int mt = 0; mt < 2; ++mt)
#pragma unroll
        for (int nt = 0; nt < 8; ++nt)
#pragma unroll
            for (int i = 0; i < 4; ++i) accO[mt][nt][i] = 0.f;
    float lsum[2][2] = {{0.f, 0.f}, {0.f, 0.f}};

    load_tile(0, 0);
    CP_COMMIT();
    for (int t = 0; t < MPAD / 128; ++t) {
        int s = t & 1;
        if (t + 1 < MPAD / 128) { load_tile(t + 1, s ^ 1); CP_COMMIT(); CP_WAIT1(); }
        else CP_WAIT0();
        __syncthreads();
        uint32_t st = sb + AQOF + s * ASTG;

        float sc[2][8][4];
#pragma unroll
        for (int mt = 0; mt < 2; ++mt)
#pragma unroll
            for (int nt = 0; nt < 8; ++nt)
#pragma unroll
                for (int i = 0; i < 4; ++i) sc[mt][nt][i] = 0.f;
#pragma unroll
        for (int ks = 0; ks < 4; ++ks) {
            uint32_t qh[2][4], ql[2][4];
#pragma unroll
            for (int mt = 0; mt < 2; ++mt) {
                uint32_t qadr = sb + (wm + mt * 16 + r16) * 144 + (ks * 16 + koff) * 2;
                ldsm4(qadr,         qh[mt][0], qh[mt][1], qh[mt][2], qh[mt][3]);
                ldsm4(qadr + 18432, ql[mt][0], ql[mt][1], ql[mt][2], ql[mt][3]);
            }
#pragma unroll
            for (int ntp = 0; ntp < 4; ++ntp) {
                uint32_t kadr = st + (wn * 64 + ntp * 16 + r16) * 144 + (ks * 16 + koff) * 2;
                uint32_t kh4[4], kl4[4];
                ldsm4(kadr,         kh4[0], kh4[1], kh4[2], kh4[3]);
                ldsm4(kadr + 18432, kl4[0], kl4[1], kl4[2], kl4[3]);
#pragma unroll
                for (int half = 0; half < 2; ++half) {
                    int nt = 2 * ntp + half;
                    uint32_t b0h = kh4[half], b1h = kh4[half + 2];
                    uint32_t b0l = kl4[half], b1l = kl4[half + 2];
#pragma unroll
                    for (int mt = 0; mt < 2; ++mt) {
                        MMA16(sc[mt][nt], qh[mt], b0h, b1h);
                        MMA16(sc[mt][nt], qh[mt], b0l, b1l);
                        MMA16(sc[mt][nt], ql[mt], b0h, b1h);
                    }
                }
            }
        }

#pragma unroll
        for (int mt = 0; mt < 2; ++mt)
#pragma unroll
            for (int nt = 0; nt < 8; ++nt) {
                int cb = t * 128 + wn * 64 + nt * 8 + 2 * tig;
                float p0 = (cb     < MAREA) ? __expf(sc[mt][nt][0]) : 0.f;
                float p1 = (cb + 1 < MAREA) ? __expf(sc[mt][nt][1]) : 0.f;
                float p2 = (cb     < MAREA) ? __expf(sc[mt][nt][2]) : 0.f;
                float p3 = (cb + 1 < MAREA) ? __expf(sc[mt][nt][3]) : 0.f;
                sc[mt][nt][0] = p0; sc[mt][nt][1] = p1;
                sc[mt][nt][2] = p2; sc[mt][nt][3] = p3;
                lsum[mt][0] += p0 + p1;
                lsum[mt][1] += p2 + p3;
            }

#pragma unroll
        for (int kk = 0; kk < 4; ++kk) {
            uint32_t pah[2][4], pal[2][4];
#pragma unroll
            for (int mt = 0; mt < 2; ++mt) {
                pah[mt][0] = packhi2(sc[mt][2 * kk][0],     sc[mt][2 * kk][1]);
                pah[mt][1] = packhi2(sc[mt][2 * kk][2],     sc[mt][2 * kk][3]);
                pah[mt][2] = packhi2(sc[mt][2 * kk + 1][0], sc[mt][2 * kk + 1][1]);
                pah[mt][3] = packhi2(sc[mt][2 * kk + 1][2], sc[mt][2 * kk + 1][3]);
                pal[mt][0] = packlo2(sc[mt][2 * kk][0],     sc[mt][2 * kk][1],     pah[mt][0]);
                pal[mt][1] = packlo2(sc[mt][2 * kk][2],     sc[mt][2 * kk][3],     pah[mt][1]);
                pal[mt][2] = packlo2(sc[mt][2 * kk + 1][0], sc[mt][2 * kk + 1][1], pah[mt][2]);
                pal[mt][3] = packlo2(sc[mt][2 * kk + 1][2], sc[mt][2 * kk + 1][3], pah[mt][3]);
            }
#pragma unroll
            for (int ntp = 0; ntp < 4; ++ntp) {
                uint32_t vadr = st + 36864 + (ntp * 16 + r16) * 272
                              + (wn * 64 + kk * 16 + koff) * 2;
                uint32_t vh4[4], vl4[4];
                ldsm4(vadr,         vh4[0], vh4[1], vh4[2], vh4[3]);
                ldsm4(vadr + 17408, vl4[0], vl4[1], vl4[2], vl4[3]);
#pragma unroll
                for (int half = 0; half < 2; ++half) {
                    int nt = 2 * ntp + half;
                    uint32_t b0h = vh4[half], b1h = vh4[half + 2];
                    uint32_t b0l = vl4[half], b1l = vl4[half + 2];
#pragma unroll
                    for (int mt = 0; mt < 2; ++mt) {
                        MMA16(accO[mt][nt], pah[mt], b0h, b1h);
                        MMA16(accO[mt][nt], pah[mt], b0l, b1l);
                        MMA16(accO[mt][nt], pal[mt], b0h, b1h);
                    }
                }
            }
        }
        __syncthreads();
    }

#pragma unroll
    for (int mt = 0; mt < 2; ++mt)
#pragma unroll
        for (int r = 0; r < 2; ++r) {
            lsum[mt][r] += __shfl_xor_sync(0xFFFFFFFF, lsum[mt][r], 1);
            lsum[mt][r] += __shfl_xor_sync(0xFFFFFFFF, lsum[mt][r], 2);
        }

    __syncthreads();
    float* Ored = (float*)(smem + AQOF);
    float* lred = (float*)(smem + AQOF + ASTG);
    if (wn == 1) {
#pragma unroll
        for (int mt = 0; mt < 2; ++mt) {
            int r0 = wm + mt * 16 + g;
#pragma unroll
            for (int nt = 0; nt < 8; ++nt) {
                int cc = nt * 8 + 2 * tig;
                Ored[r0 * 64 + cc]           = accO[mt][nt][0];
                Ored[r0 * 64 + cc + 1]       = accO[mt][nt][1];
                Ored[(r0 + 8) * 64 + cc]     = accO[mt][nt][2];
                Ored[(r0 + 8) * 64 + cc + 1] = accO[mt][nt][3];
            }
            if (tig == 0) {
                lred[r0]     = lsum[mt][0];
                lred[r0 + 8] = lsum[mt][1];
            }
        }
    }
    __syncthreads();
    if (wn == 0) {
#pragma unroll
        for (int mt = 0; mt < 2; ++mt) {
            int r0 = wm + mt * 16 + g;
            float inv0 = 1.f / (lsum[mt][0] + lred[r0]);
            float inv1 = 1.f / (lsum[mt][1] + lred[r0 + 8]);
            size_t orow0 = (size_t)(b * N_ + q0 + r0) * DIM_ + h * 64;
            size_t orow1 = (size_t)(b * N_ + q0 + r0 + 8) * DIM_ + h * 64;
#pragma unroll
            for (int nt = 0; nt < 8; ++nt) {
                int cc = nt * 8 + 2 * tig;
                float o0 = (accO[mt][nt][0] + Ored[r0 * 64 + cc])           * inv0;
                float o1 = (accO[mt][nt][1] + Ored[r0 * 64 + cc + 1])       * inv0;
                float o2 = (accO[mt][nt][2] + Ored[(r0 + 8) * 64 + cc])     * inv1;
                float o3 = (accO[mt][nt][3] + Ored[(r0 + 8) * 64 + cc + 1]) * inv1;
                uint32_t h01 = packhi2(o0, o1), h23 = packhi2(o2, o3);
                *(uint32_t*)(g_attn_hi + orow0 + cc) = h01;
                *(uint32_t*)(g_attn_hi + orow1 + cc) = h23;
                *(uint32_t*)(g_attn_lo + orow0 + cc) = packlo2(o0, o1, h01);
                *(uint32_t*)(g_attn_lo + orow1 + cc) = packlo2(o2, o3, h23);
            }
        }
    }
}

// ---------------- launch ---------------------------------------------------
extern "C" void kernel_launch(void* const* d_in, const int* in_sizes, int n_in,
                              void* d_out, int out_size) {
    const float* x     = (const float*)d_in[0];
    const float* w_qkv = (const float*)d_in[1];
    const float* w_q   = (const float*)d_in[2];
    const float* b_q   = (const float*)d_in[3];
    const float* w_k   = (const float*)d_in[4];
    const float* b_k   = (const float*)d_in[5];
    const float* w_v   = (const float*)d_in[6];
    const float* b_v   = (const float*)d_in[7];
    const float* w_o   = (const float*)d_in[8];
    const float* b_o   = (const float*)d_in[9];
    float* out = (float*)d_out;

    cudaFuncSetAttribute(gemm128_kernel, cudaFuncAttributeMaxDynamicSharedMemorySize, 2 * GSTG);
    cudaFuncSetAttribute(attn_kernel,    cudaFuncAttributeMaxDynamicSharedMemorySize, AQOF + 2 * ASTG);
    cudaFuncSetAttribute(pool_kernel,    cudaFuncAttributeMaxDynamicSharedMemorySize, 73984);

    bf16 *x_hi, *x_lo, *wqkv_hi, *wqkv_lo, *wT_hi, *wT_lo, *woT_hi, *woT_lo;
    bf16 *weffT_hi, *weffT_lo, *qkvh_hi, *qkvh_lo, *attn_hi, *attn_lo;
    float *qkvh_f, *biasqkv;
    cudaGetSymbolAddress((void**)&x_hi, g_x_hi);       cudaGetSymbolAddress((void**)&x_lo, g_x_lo);
    cudaGetSymbolAddress((void**)&wqkv_hi, g_wqkv_hi); cudaGetSymbolAddress((void**)&wqkv_lo, g_wqkv_lo);
    cudaGetSymbolAddress((void**)&wT_hi, g_wT_hi);     cudaGetSymbolAddress((void**)&wT_lo, g_wT_lo);
    cudaGetSymbolAddress((void**)&woT_hi, g_woT_hi);   cudaGetSymbolAddress((void**)&woT_lo, g_woT_lo);
    cudaGetSymbolAddress((void**)&weffT_hi, g_weffT_hi); cudaGetSymbolAddress((void**)&weffT_lo, g_weffT_lo);
    cudaGetSymbolAddress((void**)&qkvh_f, g_qkvh_f);
    cudaGetSymbolAddress((void**)&qkvh_hi, g_qkvh_hi); cudaGetSymbolAddress((void**)&qkvh_lo, g_qkvh_lo);
    cudaGetSymbolAddress((void**)&attn_hi, g_attn_hi); cudaGetSymbolAddress((void**)&attn_lo, g_attn_lo);
    cudaGetSymbolAddress((void**)&biasqkv, g_biasqkv);

    // 1. fused prep (conversions + transposes + bias)
    prep_kernel<<<NB_CONVX + NB_CONVW + NB_CONVT + 9, 256>>>(
        x, w_qkv, w_q, w_k, w_v, w_o, b_q, b_k, b_v);

    // 2. compose W_eff^T (3 segs in one launch via gridDim.z)
    {
        dim3 g(6, 6, 3);
        gemm128_kernel<<<g, 256, 2 * GSTG>>>(
            wT_hi, wT_lo, DIM_, wqkv_hi, wqkv_lo, K3,
            nullptr, weffT_hi, weffT_lo, DIM_, DIM_, nullptr,
            DIM_ * DIM_, DIM_, DIM_ * DIM_);
    }

    // 3. qh|kh|vh = x @ W_eff + bias
    {
        dim3 g(K3 / 128, ROWS_ / 128, 1);
        gemm128_kernel<<<g, 256, 2 * GSTG>>>(x_hi, x_lo, DIM_, weffT_hi, weffT_lo, DIM_,
                                             qkvh_f, qkvh_hi, qkvh_lo, K3, DIM_, biasqkv,
                                             0, 0, 0);
    }

    // 4. area pooling
    pool_kernel<<<BH_, 256, 73984>>>();

    // 5. dummy (positions attn as the 6th launch for ncu -s 5 -c 1)
    dummy_kernel<<<1, 32>>>();

    // 6. fused warp-MMA attention
    {
        dim3 g(BH_, 2);
        attn_kernel<<<g, 256, AQOF + 2 * ASTG>>>();
    }

    // 7. out = attn @ w_o + b_o
    {
        dim3 g(DIM_ / 128, ROWS_ / 128, 1);
        gemm128_kernel<<<g, 256, 2 * GSTG>>>(attn_hi, attn_lo, DIM_, woT_hi, woT_lo, DIM_,
                                             out, nullptr, nullptr, DIM_, DIM_, b_o,
                                             0, 0, 0);
    }
}

// round 8
// speedup vs baseline: 2.8687x; 1.7568x over previous
#include <cuda_runtime.h>
#include <cuda_bf16.h>
#include <cstdint>

#define B_     16
#define N_     256
#define DIM_   768
#define HEADS_ 12
#define DHEAD_ 64
#define BH_    192
#define MAREA  2025
#define MPAD   2048
#define ROWS_  4096
#define K3     2304

typedef __nv_bfloat16 bf16;

// ---------------- device global scratch ----------------
__device__ float g_biasqkv[K3];
__device__ float g_dummyv;
__device__ bf16  g_x_hi[ROWS_*DIM_],   g_x_lo[ROWS_*DIM_];
__device__ bf16  g_wqkv_hi[DIM_*K3],   g_wqkv_lo[DIM_*K3];
__device__ bf16  g_wT_hi[3*DIM_*DIM_], g_wT_lo[3*DIM_*DIM_];
__device__ bf16  g_woT_hi[DIM_*DIM_],  g_woT_lo[DIM_*DIM_];
__device__ bf16  g_weffT_hi[K3*DIM_],  g_weffT_lo[K3*DIM_];
__device__ float g_qkvh_f[(size_t)ROWS_*K3];
__device__ bf16  g_qkvh_hi[(size_t)ROWS_*K3], g_qkvh_lo[(size_t)ROWS_*K3];
__device__ bf16  g_ka_hi[(size_t)BH_*MPAD*DHEAD_], g_ka_lo[(size_t)BH_*MPAD*DHEAD_];
__device__ bf16  g_vt_hi[(size_t)BH_*DHEAD_*MPAD], g_vt_lo[(size_t)BH_*DHEAD_*MPAD];
__device__ bf16  g_attn_hi[(size_t)ROWS_*DIM_],    g_attn_lo[(size_t)ROWS_*DIM_];

// ---------------- helpers ----------------
__device__ __forceinline__ uint32_t smem_u32(const void* p) {
    uint32_t a;
    asm("{ .reg .u64 t; cvta.to.shared.u64 t, %1; cvt.u32.u64 %0, t; }" : "=r"(a) : "l"(p));
    return a;
}
__device__ __forceinline__ uint32_t packhi2(float x, float y) {
    __nv_bfloat162 t = __floats2bfloat162_rn(x, y);
    return *(uint32_t*)&t;
}
__device__ __forceinline__ uint32_t packlo2(float x, float y, uint32_t hp) {
    __nv_bfloat162 h = *(__nv_bfloat162*)&hp;
    __nv_bfloat162 t = __floats2bfloat162_rn(x - __bfloat162float(h.x),
                                             y - __bfloat162float(h.y));
    return *(uint32_t*)&t;
}

#define MMA16(d, a, b0, b1) \
    asm volatile("mma.sync.aligned.m16n8k16.row.col.f32.bf16.bf16.f32 " \
        "{%0,%1,%2,%3}, {%4,%5,%6,%7}, {%8,%9}, {%0,%1,%2,%3};" \
        : "+f"((d)[0]), "+f"((d)[1]), "+f"((d)[2]), "+f"((d)[3]) \
        : "r"((a)[0]), "r"((a)[1]), "r"((a)[2]), "r"((a)[3]), "r"(b0), "r"(b1))

__device__ __forceinline__ void ldsm4(uint32_t addr, uint32_t& r0, uint32_t& r1,
                                      uint32_t& r2, uint32_t& r3) {
    asm volatile("ldmatrix.sync.aligned.m8n8.x4.shared.b16 {%0,%1,%2,%3}, [%4];"
                 : "=r"(r0), "=r"(r1), "=r"(r2), "=r"(r3) : "r"(addr));
}
__device__ __forceinline__ void cpasync16(uint32_t saddr, const void* g) {
    asm volatile("cp.async.cg.shared.global [%0], [%1], 16;" :: "r"(saddr), "l"(g));
}
#define CP_COMMIT() asm volatile("cp.async.commit_group;" ::: "memory")
#define CP_WAIT0()  asm volatile("cp.async.wait_group 0;" ::: "memory")
#define CP_WAIT1()  asm volatile("cp.async.wait_group 1;" ::: "memory")

// ---------------- fused prep kernel (bias + conversions + transposes) -----
#define NB_CONVX 12288
#define NB_CONVW 6912
#define NB_CONVT 2304
__global__ __launch_bounds__(256)
void prep_kernel(const float* __restrict__ x, const float* __restrict__ w_qkv,
                 const float* __restrict__ w_q, const float* __restrict__ w_k,
                 const float* __restrict__ w_v, const float* __restrict__ w_o,
                 const float* __restrict__ bq, const float* __restrict__ bk,
                 const float* __restrict__ bv) {
    __shared__ float tile[32][33];
    int bx = blockIdx.x, t = threadIdx.x;
    if (bx < NB_CONVX) {
        int i = bx * 256 + t;
        float v = x[i];
        bf16 h = __float2bfloat16(v);
        g_x_hi[i] = h;
        g_x_lo[i] = __float2bfloat16(v - __bfloat162float(h));
    } else if (bx < NB_CONVX + NB_CONVW) {
        int i = (bx - NB_CONVX) * 256 + t;
        float v = w_qkv[i];
        bf16 h = __float2bfloat16(v);
        g_wqkv_hi[i] = h;
        g_wqkv_lo[i] = __float2bfloat16(v - __bfloat162float(h));
    } else if (bx < NB_CONVX + NB_CONVW + NB_CONVT) {
        int id = bx - (NB_CONVX + NB_CONVW);
        int seg = id / 576, rem = id % 576;
        int c0 = (rem % 24) * 32, r0 = (rem / 24) * 32;
        const float* src = (seg == 0) ? w_q : (seg == 1) ? w_k : (seg == 2) ? w_v : w_o;
        bf16* hi = (seg < 3) ? (g_wT_hi + (size_t)seg * DIM_ * DIM_) : g_woT_hi;
        bf16* lo = (seg < 3) ? (g_wT_lo + (size_t)seg * DIM_ * DIM_) : g_woT_lo;
        int tx = t & 31, ty = t >> 5;
#pragma unroll
        for (int i = 0; i < 4; ++i)
            tile[ty + i * 8][tx] = src[(size_t)(r0 + ty + i * 8) * DIM_ + c0 + tx];
        __syncthreads();
#pragma unroll
        for (int i = 0; i < 4; ++i) {
            float v = tile[tx][ty + i * 8];
            size_t o = (size_t)(c0 + ty + i * 8) * DIM_ + r0 + tx;
            bf16 h = __float2bfloat16(v);
            hi[o] = h;
            lo[o] = __float2bfloat16(v - __bfloat162float(h));
        }
    } else {
        int idx = (bx - (NB_CONVX + NB_CONVW + NB_CONVT)) * 256 + t;
        int seg = idx / 768;
        const float* s = (seg == 0) ? bq : (seg == 1) ? bk : bv;
        g_biasqkv[idx] = s[idx % 768];
    }
}

__global__ void dummy_kernel() {
    if (threadIdx.x == 0) g_dummyv = 1.f;
}

// ---------------- 128x128 warp-MMA GEMM, BK=32, 2 CTAs/SM -----------------
#define GSTG 40960
__global__ __launch_bounds__(256, 2)
void gemm128_kernel(const bf16* __restrict__ Ah, const bf16* __restrict__ Al, int lda,
                    const bf16* __restrict__ Bh, const bf16* __restrict__ Bl, int ldb,
                    float* __restrict__ Cf, bf16* __restrict__ Chi, bf16* __restrict__ Clo,
                    int ldc, int K, const float* __restrict__ bias,
                    int sAz, int sBz, int sCz) {
    extern __shared__ char smem[];
    uint32_t sb = smem_u32(smem);
    int z = blockIdx.z;
    Ah += (size_t)z * sAz; Al += (size_t)z * sAz;
    Bh += (size_t)z * sBz; Bl += (size_t)z * sBz;
    if (Cf)  Cf  += (size_t)z * sCz;
    if (Chi) { Chi += (size_t)z * sCz; Clo += (size_t)z * sCz; }

    int tid = threadIdx.x, lane = tid & 31, wid = tid >> 5;
    int g = lane >> 2, tig = lane & 3;
    int wm = (wid >> 1) * 32, wn = (wid & 1) * 64;
    int m0 = blockIdx.y * 128, n0 = blockIdx.x * 128;
    int r16 = lane & 15, koff = (lane >> 4) * 8;

    float acc[2][8][4];
#pragma unroll
    for (int mt = 0; mt < 2; ++mt)
#pragma unroll
        for (int nt = 0; nt < 8; ++nt)
#pragma unroll
            for (int i = 0; i < 4; ++i) acc[mt][nt][i] = 0.f;

    auto load_chunk = [&](int kc, int s) {
        uint32_t st = sb + s * GSTG;
#pragma unroll
        for (int it = 0; it < 2; ++it) {
            int idx = tid + it * 256;
            int row = idx >> 2, seg8 = (idx & 3) * 8;
            uint32_t so = row * 80 + seg8 * 2;
            size_t ga = (size_t)(m0 + row) * lda + kc + seg8;
            size_t gb = (size_t)(n0 + row) * ldb + kc + seg8;
            cpasync16(st +         so, Ah + ga);
            cpasync16(st + 10240 + so, Al + ga);
            cpasync16(st + 20480 + so, Bh + gb);
            cpasync16(st + 30720 + so, Bl + gb);
        }
    };

    int nch = K / 32;
    load_chunk(0, 0);
    CP_COMMIT();
    for (int c = 0; c < nch; ++c) {
        int s = c & 1;
        if (c + 1 < nch) { load_chunk((c + 1) * 32, s ^ 1); CP_COMMIT(); CP_WAIT1(); }
        else CP_WAIT0();
        __syncthreads();
        uint32_t st = sb + s * GSTG;
#pragma unroll
        for (int ks = 0; ks < 2; ++ks) {
            uint32_t ah[2][4], al[2][4];
#pragma unroll
            for (int mt = 0; mt < 2; ++mt) {
                uint32_t aadr = st + (wm + mt * 16 + r16) * 80 + (ks * 16 + koff) * 2;
                ldsm4(aadr,         ah[mt][0], ah[mt][1], ah[mt][2], ah[mt][3]);
                ldsm4(aadr + 10240, al[mt][0], al[mt][1], al[mt][2], al[mt][3]);
            }
#pragma unroll
            for (int ntp = 0; ntp < 4; ++ntp) {
                uint32_t badr = st + 20480 + (wn + ntp * 16 + r16) * 80 + (ks * 16 + koff) * 2;
                uint32_t bh4[4], bl4[4];
                ldsm4(badr,         bh4[0], bh4[1], bh4[2], bh4[3]);
                ldsm4(badr + 10240, bl4[0], bl4[1], bl4[2], bl4[3]);
#pragma unroll
                for (int half = 0; half < 2; ++half) {
                    int nt = 2 * ntp + half;
                    uint32_t bh0 = bh4[half], bh1 = bh4[half + 2];
                    uint32_t bl0 = bl4[half], bl1 = bl4[half + 2];
#pragma unroll
                    for (int mt = 0; mt < 2; ++mt) {
                        MMA16(acc[mt][nt], ah[mt], bh0, bh1);
                        MMA16(acc[mt][nt], ah[mt], bl0, bl1);
                        MMA16(acc[mt][nt], al[mt], bh0, bh1);
                    }
                }
            }
        }
        __syncthreads();
    }
#pragma unroll
    for (int mt = 0; mt < 2; ++mt)
#pragma unroll
        for (int nt = 0; nt < 8; ++nt) {
            int row = m0 + wm + mt * 16 + g;
            int col = n0 + wn + nt * 8 + 2 * tig;
            float v0 = acc[mt][nt][0], v1 = acc[mt][nt][1];
            float v2 = acc[mt][nt][2], v3 = acc[mt][nt][3];
            if (bias) {
                float b0v = bias[col], b1v = bias[col + 1];
                v0 += b0v; v1 += b1v; v2 += b0v; v3 += b1v;
            }
            if (Cf) {
                *(float2*)(Cf + (size_t)row * ldc + col)       = make_float2(v0, v1);
                *(float2*)(Cf + (size_t)(row + 8) * ldc + col) = make_float2(v2, v3);
            }
            if (Chi) {
                uint32_t h01 = packhi2(v0, v1), h23 = packhi2(v2, v3);
                *(uint32_t*)(Chi + (size_t)row * ldc + col)       = h01;
                *(uint32_t*)(Chi + (size_t)(row + 8) * ldc + col) = h23;
                *(uint32_t*)(Clo + (size_t)row * ldc + col)       = packlo2(v0, v1, h01);
                *(uint32_t*)(Clo + (size_t)(row + 8) * ldc + col) = packlo2(v2, v3, h23);
            }
        }
}

// ---------------- area pooling: grid (192, 8), 8 channels/block -----------
// SAT per (bh, channel) in static smem [8][289] (9.2 KB) -> high occupancy.
__global__ __launch_bounds__(256)
void pool_kernel() {
    int bh = blockIdx.x, cbase = blockIdx.y * 8;
    int b = bh / HEADS_, h = bh % HEADS_;
    __shared__ float sat[8][289];
    int t = threadIdx.x;
    const int cnts[9] = {256, 240, 224, 240, 225, 210, 224, 210, 196};

    for (int pass = 0; pass < 2; ++pass) {
        const float* base = g_qkvh_f + (size_t)(b * N_) * K3 + (pass ? 2 * DIM_ : DIM_)
                          + h * DHEAD_ + cbase;
        // phase 1: row prefix sums (128 threads: 8 ch x 16 rows)
        if (t < 128) {
            int ch = t & 7, row = t >> 3;
            if (row == 0)
#pragma unroll
                for (int x = 0; x < 17; ++x) sat[ch][x] = 0.f;
            sat[ch][(row + 1) * 17] = 0.f;
            float vals[16];
#pragma unroll
            for (int x = 0; x < 16; ++x)
                vals[x] = base[(size_t)(row * 16 + x) * K3 + ch];
            float acc = 0.f;
#pragma unroll
            for (int x = 0; x < 16; ++x) {
                acc += vals[x];
                sat[ch][(row + 1) * 17 + x + 1] = acc;
            }
        }
        __syncthreads();
        // phase 2: column prefix (128 threads: 8 ch x 16 cols)
        if (t < 128) {
            int ch = t >> 4, col = (t & 15) + 1;
            float acc = 0.f;
#pragma unroll
            for (int y = 1; y <= 16; ++y) {
                acc += sat[ch][y * 17 + col];
                sat[ch][y * 17 + col] = acc;
            }
        }
        __syncthreads();
        // phase 3: all areas; 8 channels packed into 16B stores for K-array
        for (int m = t; m < MPAD; m += 256) {
            float scale = 0.f;
            int y0 = 0, x0 = 0, ah = 1, aw = 1;
            bool valid = (m < MAREA);
            if (valid) {
                int rem = m, seg = 0;
                while (rem >= cnts[seg]) { rem -= cnts[seg]; ++seg; }
                ah = seg / 3 + 1; aw = seg % 3 + 1;
                int w = 17 - aw;
                y0 = rem / w; x0 = rem % w;
                scale = (pass == 0) ? 1.f / (float)(ah * aw) : 1.f;
            }
            int iA = (y0 + ah) * 17 + x0 + aw, iB = y0 * 17 + x0 + aw;
            int iC = (y0 + ah) * 17 + x0,      iD = y0 * 17 + x0;
            bf16 hv[8], lv[8];
#pragma unroll
            for (int c = 0; c < 8; ++c) {
                float s = 0.f;
                if (valid)
                    s = (sat[c][iA] - sat[c][iB] - sat[c][iC] + sat[c][iD]) * scale;
                hv[c] = __float2bfloat16(s);
                lv[c] = __float2bfloat16(s - __bfloat162float(hv[c]));
            }
            if (pass == 0) {
                size_t o = ((size_t)bh * MPAD + m) * DHEAD_ + cbase;
                *(uint4*)(g_ka_hi + o) = *(uint4*)hv;
                *(uint4*)(g_ka_lo + o) = *(uint4*)lv;
            } else {
#pragma unroll
                for (int c = 0; c < 8; ++c) {
                    size_t o = ((size_t)bh * DHEAD_ + cbase + c) * MPAD + m;
                    g_vt_hi[o] = hv[c];
                    g_vt_lo[o] = lv[c];
                }
            }
        }
        __syncthreads();
    }
}

// ---------------- fused warp-MMA attention (unchanged, proven) ------------
#define ASTG 71680
#define AQOF 36864
__global__ __launch_bounds__(256)
void attn_kernel() {
    extern __shared__ char smem[];
    uint32_t sb = smem_u32(smem);
    int tid = threadIdx.x, lane = tid & 31, wid = tid >> 5;
    int g = lane >> 2, tig = lane & 3;
    int wm = (wid >> 1) * 32, wn = wid & 1;
    int bh = blockIdx.x, q0 = blockIdx.y * 128;
    int b = bh / HEADS_, h = bh % HEADS_;
    int r16 = lane & 15, koff = (lane >> 4) * 8;

    bf16* Qs = (bf16*)smem;
#pragma unroll
    for (int it = 0; it < 4; ++it) {
        int idx = tid + it * 256;
        int row = idx >> 3, seg = (idx & 7) * 8;
        size_t src = (size_t)(b * N_ + q0 + row) * K3 + h * 64 + seg;
        *(uint4*)(Qs + row * 72 + seg)        = *(const uint4*)(g_qkvh_hi + src);
        *(uint4*)(Qs + 9216 + row * 72 + seg) = *(const uint4*)(g_qkvh_lo + src);
    }

    const bf16* kaH = g_ka_hi + (size_t)bh * MPAD * 64;
    const bf16* kaL = g_ka_lo + (size_t)bh * MPAD * 64;
    const bf16* vtH = g_vt_hi + (size_t)bh * 64 * MPAD;
    const bf16* vtL = g_vt_lo + (size_t)bh * 64 * MPAD;

    int lrow = tid >> 3, lseg = (tid & 7) * 8;
    int vlrow = tid >> 4, vlseg = (tid & 15) * 8;
    auto load_tile = [&](int t, int s) {
        uint32_t st = sb + AQOF + s * ASTG;
#pragma unroll
        for (int it = 0; it < 4; ++it) {
            int row = lrow + it * 32;
            uint32_t so = row * 144 + lseg * 2;
            size_t gk = (size_t)(t * 128 + row) * 64 + lseg;
            cpasync16(st +         so, kaH + gk);
            cpasync16(st + 18432 + so, kaL + gk);
            int vrow = vlrow + it * 16;
            uint32_t vo = vrow * 272 + vlseg * 2;
            size_t gv = (size_t)vrow * MPAD + t * 128 + vlseg;
            cpasync16(st + 36864 + vo, vtH + gv);
            cpasync16(st + 54272 + vo, vtL + gv);
        }
    };

    float accO[2][8][4];
#pragma unroll
    for (int mt = 0; mt < 2; ++mt)
#pragma unroll
        for (int nt = 0; nt < 8; ++nt)
#pragma unroll
            for (int i = 0; i < 4; ++i) accO[mt][nt][i] = 0.f;
    float lsum[2][2] = {{0.f, 0.f}, {0.f, 0.f}};

    load_tile(0, 0);
    CP_COMMIT();
    for (int t = 0; t < MPAD / 128; ++t) {
        int s = t & 1;
        if (t + 1 < MPAD / 128) { load_tile(t + 1, s ^ 1); CP_COMMIT(); CP_WAIT1(); }
        else CP_WAIT0();
        __syncthreads();
        uint32_t st = sb + AQOF + s * ASTG;

        float sc[2][8][4];
#pragma unroll
        for (int mt = 0; mt < 2; ++mt)
#pragma unroll
            for (int nt = 0; nt < 8; ++nt)
#pragma unroll
                for (int i = 0; i < 4; ++i) sc[mt][nt][i] = 0.f;
#pragma unroll
        for (int ks = 0; ks < 4; ++ks) {
            uint32_t qh[2][4], ql[2][4];
#pragma unroll
            for (int mt = 0; mt < 2; ++mt) {
                uint32_t qadr = sb + (wm + mt * 16 + r16) * 144 + (ks * 16 + koff) * 2;
                ldsm4(qadr,         qh[mt][0], qh[mt][1], qh[mt][2], qh[mt][3]);
                ldsm4(qadr + 18432, ql[mt][0], ql[mt][1], ql[mt][2], ql[mt][3]);
            }
#pragma unroll
            for (int ntp = 0; ntp < 4; ++ntp) {
                uint32_t kadr = st + (wn * 64 + ntp * 16 + r16) * 144 + (ks * 16 + koff) * 2;
                uint32_t kh4[4], kl4[4];
                ldsm4(kadr,         kh4[0], kh4[1], kh4[2], kh4[3]);
                ldsm4(kadr + 18432, kl4[0], kl4[1], kl4[2], kl4[3]);
#pragma unroll
                for (int half = 0; half < 2; ++half) {
                    int nt = 2 * ntp + half;
                    uint32_t b0h = kh4[half], b1h = kh4[half + 2];
                    uint32_t b0l = kl4[half], b1l = kl4[half + 2];
#pragma unroll
                    for (int mt = 0; mt < 2; ++mt) {
                        MMA16(sc[mt][nt], qh[mt], b0h, b1h);
                        MMA16(sc[mt][nt], qh[mt], b0l, b1l);
                        MMA16(sc[mt][nt], ql[mt], b0h, b1h);
                    }
                }
            }
        }

#pragma unroll
        for (int mt = 0; mt < 2; ++mt)
#pragma unroll
            for (int nt = 0; nt < 8; ++nt) {
                int cb = t * 128 + wn * 64 + nt * 8 + 2 * tig;
                float p0 = (cb     < MAREA) ? __expf(sc[mt][nt][0]) : 0.f;
                float p1 = (cb + 1 < MAREA) ? __expf(sc[mt][nt][1]) : 0.f;
                float p2 = (cb     < MAREA) ? __expf(sc[mt][nt][2]) : 0.f;
                float p3 = (cb + 1 < MAREA) ? __expf(sc[mt][nt][3]) : 0.f;
                sc[mt][nt][0] = p0; sc[mt][nt][1] = p1;
                sc[mt][nt][2] = p2; sc[mt][nt][3] = p3;
                lsum[mt][0] += p0 + p1;
                lsum[mt][1] += p2 + p3;
            }

#pragma unroll
        for (int kk = 0; kk < 4; ++kk) {
            uint32_t pah[2][4], pal[2][4];
#pragma unroll
            for (int mt = 0; mt < 2; ++mt) {
                pah[mt][0] = packhi2(sc[mt][2 * kk][0],     sc[mt][2 * kk][1]);
                pah[mt][1] = packhi2(sc[mt][2 * kk][2],     sc[mt][2 * kk][3]);
                pah[mt][2] = packhi2(sc[mt][2 * kk + 1][0], sc[mt][2 * kk + 1][1]);
                pah[mt][3] = packhi2(sc[mt][2 * kk + 1][2], sc[mt][2 * kk + 1][3]);
                pal[mt][0] = packlo2(sc[mt][2 * kk][0],     sc[mt][2 * kk][1],     pah[mt][0]);
                pal[mt][1] = packlo2(sc[mt][2 * kk][2],     sc[mt][2 * kk][3],     pah[mt][1]);
                pal[mt][2] = packlo2(sc[mt][2 * kk + 1][0], sc[mt][2 * kk + 1][1], pah[mt][2]);
                pal[mt][3] = packlo2(sc[mt][2 * kk + 1][2], sc[mt][2 * kk + 1][3], pah[mt][3]);
            }
#pragma unroll
            for (int ntp = 0; ntp < 4; ++ntp) {
                uint32_t vadr = st + 36864 + (ntp * 16 + r16) * 272
                              + (wn * 64 + kk * 16 + koff) * 2;
                uint32_t vh4[4], vl4[4];
                ldsm4(vadr,         vh4[0], vh4[1], vh4[2], vh4[3]);
                ldsm4(vadr + 17408, vl4[0], vl4[1], vl4[2], vl4[3]);
#pragma unroll
                for (int half = 0; half < 2; ++half) {
                    int nt = 2 * ntp + half;
                    uint32_t b0h = vh4[half], b1h = vh4[half + 2];
                    uint32_t b0l = vl4[half], b1l = vl4[half + 2];
#pragma unroll
                    for (int mt = 0; mt < 2; ++mt) {
                        MMA16(accO[mt][nt], pah[mt], b0h, b1h);
                        MMA16(accO[mt][nt], pah[mt], b0l, b1l);
                        MMA16(accO[mt][nt], pal[mt], b0h, b1h);
                    }
                }
            }
        }
        __syncthreads();
    }

#pragma unroll
    for (int mt = 0; mt < 2; ++mt)
#pragma unroll
        for (int r = 0; r < 2; ++r) {
            lsum[mt][r] += __shfl_xor_sync(0xFFFFFFFF, lsum[mt][r], 1);
            lsum[mt][r] += __shfl_xor_sync(0xFFFFFFFF, lsum[mt][r], 2);
        }

    __syncthreads();
    float* Ored = (float*)(smem + AQOF);
    float* lred = (float*)(smem + AQOF + ASTG);
    if (wn == 1) {
#pragma unroll
        for (int mt = 0; mt < 2; ++mt) {
            int r0 = wm + mt * 16 + g;
#pragma unroll
            for (int nt = 0; nt < 8; ++nt) {
                int cc = nt * 8 + 2 * tig;
                Ored[r0 * 64 + cc]           = accO[mt][nt][0];
                Ored[r0 * 64 + cc + 1]       = accO[mt][nt][1];
                Ored[(r0 + 8) * 64 + cc]     = accO[mt][nt][2];
                Ored[(r0 + 8) * 64 + cc + 1] = accO[mt][nt][3];
            }
            if (tig == 0) {
                lred[r0]     = lsum[mt][0];
                lred[r0 + 8] = lsum[mt][1];
            }
        }
    }
    __syncthreads();
    if (wn == 0) {
#pragma unroll
        for (int mt = 0; mt < 2; ++mt) {
            int r0 = wm + mt * 16 + g;
            float inv0 = 1.f / (lsum[mt][0] + lred[r0]);
            float inv1 = 1.f / (lsum[mt][1] + lred[r0 + 8]);
            size_t orow0 = (size_t)(b * N_ + q0 + r0) * DIM_ + h * 64;
            size_t orow1 = (size_t)(b * N_ + q0 + r0 + 8) * DIM_ + h * 64;
#pragma unroll
            for (int nt = 0; nt < 8; ++nt) {
                int cc = nt * 8 + 2 * tig;
                float o0 = (accO[mt][nt][0] + Ored[r0 * 64 + cc])           * inv0;
                float o1 = (accO[mt][nt][1] + Ored[r0 * 64 + cc + 1])       * inv0;
                float o2 = (accO[mt][nt][2] + Ored[(r0 + 8) * 64 + cc])     * inv1;
                float o3 = (accO[mt][nt][3] + Ored[(r0 + 8) * 64 + cc + 1]) * inv1;
                uint32_t h01 = packhi2(o0, o1), h23 = packhi2(o2, o3);
                *(uint32_t*)(g_attn_hi + orow0 + cc) = h01;
                *(uint32_t*)(g_attn_hi + orow1 + cc) = h23;
                *(uint32_t*)(g_attn_lo + orow0 + cc) = packlo2(o0, o1, h01);
                *(uint32_t*)(g_attn_lo + orow1 + cc) = packlo2(o2, o3, h23);
            }
        }
    }
}

// ---------------- launch ---------------------------------------------------
extern "C" void kernel_launch(void* const* d_in, const int* in_sizes, int n_in,
                              void* d_out, int out_size) {
    const float* x     = (const float*)d_in[0];
    const float* w_qkv = (const float*)d_in[1];
    const float* w_q   = (const float*)d_in[2];
    const float* b_q   = (const float*)d_in[3];
    const float* w_k   = (const float*)d_in[4];
    const float* b_k   = (const float*)d_in[5];
    const float* w_v   = (const float*)d_in[6];
    const float* b_v   = (const float*)d_in[7];
    const float* w_o   = (const float*)d_in[8];
    const float* b_o   = (const float*)d_in[9];
    float* out = (float*)d_out;

    cudaFuncSetAttribute(gemm128_kernel, cudaFuncAttributeMaxDynamicSharedMemorySize, 2 * GSTG);
    cudaFuncSetAttribute(attn_kernel,    cudaFuncAttributeMaxDynamicSharedMemorySize, AQOF + 2 * ASTG);

    bf16 *x_hi, *x_lo, *wqkv_hi, *wqkv_lo, *wT_hi, *wT_lo, *woT_hi, *woT_lo;
    bf16 *weffT_hi, *weffT_lo, *qkvh_hi, *qkvh_lo, *attn_hi, *attn_lo;
    float *qkvh_f, *biasqkv;
    cudaGetSymbolAddress((void**)&x_hi, g_x_hi);       cudaGetSymbolAddress((void**)&x_lo, g_x_lo);
    cudaGetSymbolAddress((void**)&wqkv_hi, g_wqkv_hi); cudaGetSymbolAddress((void**)&wqkv_lo, g_wqkv_lo);
    cudaGetSymbolAddress((void**)&wT_hi, g_wT_hi);     cudaGetSymbolAddress((void**)&wT_lo, g_wT_lo);
    cudaGetSymbolAddress((void**)&woT_hi, g_woT_hi);   cudaGetSymbolAddress((void**)&woT_lo, g_woT_lo);
    cudaGetSymbolAddress((void**)&weffT_hi, g_weffT_hi); cudaGetSymbolAddress((void**)&weffT_lo, g_weffT_lo);
    cudaGetSymbolAddress((void**)&qkvh_f, g_qkvh_f);
    cudaGetSymbolAddress((void**)&qkvh_hi, g_qkvh_hi); cudaGetSymbolAddress((void**)&qkvh_lo, g_qkvh_lo);
    cudaGetSymbolAddress((void**)&attn_hi, g_attn_hi); cudaGetSymbolAddress((void**)&attn_lo, g_attn_lo);
    cudaGetSymbolAddress((void**)&biasqkv, g_biasqkv);

    // 1. fused prep
    prep_kernel<<<NB_CONVX + NB_CONVW + NB_CONVT + 9, 256>>>(
        x, w_qkv, w_q, w_k, w_v, w_o, b_q, b_k, b_v);

    // 2. compose W_eff^T (3 segs via gridDim.z)
    {
        dim3 g(6, 6, 3);
        gemm128_kernel<<<g, 256, 2 * GSTG>>>(
            wT_hi, wT_lo, DIM_, wqkv_hi, wqkv_lo, K3,
            nullptr, weffT_hi, weffT_lo, DIM_, DIM_, nullptr,
            DIM_ * DIM_, DIM_, DIM_ * DIM_);
    }

    // 3. qh|kh|vh = x @ W_eff + bias
    {
        dim3 g(K3 / 128, ROWS_ / 128, 1);
        gemm128_kernel<<<g, 256, 2 * GSTG>>>(x_hi, x_lo, DIM_, weffT_hi, weffT_lo, DIM_,
                                             qkvh_f, qkvh_hi, qkvh_lo, K3, DIM_, biasqkv,
                                             0, 0, 0);
    }

    // 4. area pooling (8x finer grid)
    {
        dim3 g(BH_, 8);
        pool_kernel<<<g, 256>>>();
    }

    // 5. dummy (keeps attn as launch #6 for ncu -s 5 -c 1)
    dummy_kernel<<<1, 32>>>();

    // 6. fused warp-MMA attention
    {
        dim3 g(BH_, 2);
        attn_kernel<<<g, 256, AQOF + 2 * ASTG>>>();
    }

    // 7. out = attn @ w_o + b_o
    {
        dim3 g(DIM_ / 128, ROWS_ / 128, 1);
        gemm128_kernel<<<g, 256, 2 * GSTG>>>(attn_hi, attn_lo, DIM_, woT_hi, woT_lo, DIM_,
                                             out, nullptr, nullptr, DIM_, DIM_, b_o,
                                             0, 0, 0);
    }
}